// round 2
// baseline (speedup 1.0000x reference)
#include <cuda_runtime.h>
#include <math.h>

#define B_ 2
#define S_ 2048
#define DM_ 1024
#define H_ 16
#define HD_ 64
#define MTOT (B_ * S_)      // 4096
#define ATT_SCALE 0.125f    // 64^-0.5

// Scratch (allocation-free: __device__ globals)
__device__ float g_Q[(size_t)B_ * H_ * S_ * HD_];   // head-major [B,H,S,HD]
__device__ float g_K[(size_t)B_ * H_ * S_ * HD_];
__device__ float g_V[(size_t)B_ * H_ * S_ * HD_];
__device__ float g_O[(size_t)B_ * S_ * DM_];        // row-major [B*S, DM]

// ---------------------------------------------------------------------------
// GEMM: Y[m,n] = sum_k X[m,k] * W[n,k] + bias[n]
// MODE 0: X = g_O (internal), Y = param (row-major [MTOT, DM])  -> final proj
// MODE 1/2/3: X = param, Y = g_Q/g_K/g_V in head-major [B,H,S,HD]
// 128x128 tile, BK=8, 256 threads, 8x8 microtile.
// ---------------------------------------------------------------------------
template <int MODE>
__global__ __launch_bounds__(256, 2)
void gemm_kernel(const float* __restrict__ Xin, const float* __restrict__ W,
                 const float* __restrict__ bias, float* __restrict__ Yout)
{
    const int Kdim = DM_;
    const float* X = (MODE == 0) ? (const float*)g_O : Xin;

    __shared__ float As[8][132];
    __shared__ float Bs[8][132];

    const int tid = threadIdx.x;
    const int tm = tid >> 4;          // 0..15
    const int tn = tid & 15;          // 0..15
    const int bm = blockIdx.y * 128;
    const int bn = blockIdx.x * 128;

    float acc[8][8];
#pragma unroll
    for (int i = 0; i < 8; i++)
#pragma unroll
        for (int j = 0; j < 8; j++) acc[i][j] = 0.0f;

    const int lrow = tid >> 1;        // 0..127
    const int lc4  = (tid & 1) * 4;   // 0 or 4
    const float* Xp = X + (size_t)(bm + lrow) * Kdim + lc4;
    const float* Wp = W + (size_t)(bn + lrow) * Kdim + lc4;

    for (int k0 = 0; k0 < Kdim; k0 += 8) {
        float4 xa = *(const float4*)(Xp + k0);
        float4 wa = *(const float4*)(Wp + k0);
        As[lc4 + 0][lrow] = xa.x; As[lc4 + 1][lrow] = xa.y;
        As[lc4 + 2][lrow] = xa.z; As[lc4 + 3][lrow] = xa.w;
        Bs[lc4 + 0][lrow] = wa.x; Bs[lc4 + 1][lrow] = wa.y;
        Bs[lc4 + 2][lrow] = wa.z; Bs[lc4 + 3][lrow] = wa.w;
        __syncthreads();

#pragma unroll
        for (int kk = 0; kk < 8; kk++) {
            float a[8], bb[8];
            *(float4*)(a)      = *(const float4*)&As[kk][tm * 8];
            *(float4*)(a + 4)  = *(const float4*)&As[kk][tm * 8 + 4];
            *(float4*)(bb)     = *(const float4*)&Bs[kk][tn * 8];
            *(float4*)(bb + 4) = *(const float4*)&Bs[kk][tn * 8 + 4];
#pragma unroll
            for (int i = 0; i < 8; i++)
#pragma unroll
                for (int j = 0; j < 8; j++)
                    acc[i][j] += a[i] * bb[j];
        }
        __syncthreads();
    }

#pragma unroll
    for (int i = 0; i < 8; i++) {
        const int m = bm + tm * 8 + i;
#pragma unroll
        for (int j = 0; j < 8; j++) {
            const int n = bn + tn * 8 + j;
            const float v = acc[i][j] + bias[n];
            if (MODE == 0) {
                Yout[(size_t)m * DM_ + n] = v;
            } else {
                float* dst = (MODE == 1) ? g_Q : (MODE == 2) ? g_K : g_V;
                const int b_ = m >> 11;          // m / S
                const int s_ = m & (S_ - 1);
                const int h_ = n >> 6;           // n / HD
                const int d_ = n & (HD_ - 1);
                dst[((((size_t)b_ * H_ + h_) * S_) + s_) * HD_ + d_] = v;
            }
        }
    }
}

// ---------------------------------------------------------------------------
// Attention with softmax-one. One thread = one query row.
// grid: (S/128, B*H), block: 128 threads.
// Online softmax with virtual zero logit: init m=0, l=1 reproduces
// exp(x-m) / (exp(-m) + sum exp(x-m)) exactly.
// ---------------------------------------------------------------------------
#define TK 32

__global__ __launch_bounds__(128, 2)
void attn_kernel()
{
    __shared__ float Ks[TK * HD_];
    __shared__ float Vs[TK * HD_];

    const int tid = threadIdx.x;
    const int bh  = blockIdx.y;                 // b*H + h
    const int q   = blockIdx.x * 128 + tid;

    const float* qp = g_Q + ((size_t)bh * S_ + q) * HD_;
    float qr[HD_];
#pragma unroll
    for (int i = 0; i < 16; i++) {
        float4 t = ((const float4*)qp)[i];
        qr[4 * i + 0] = t.x; qr[4 * i + 1] = t.y;
        qr[4 * i + 2] = t.z; qr[4 * i + 3] = t.w;
    }

    float acc[HD_];
#pragma unroll
    for (int d = 0; d < HD_; d++) acc[d] = 0.0f;
    float mrun = 0.0f;   // virtual zero logit
    float lrun = 1.0f;   // exp(0 - 0)

    const float* Kb = g_K + (size_t)bh * S_ * HD_;
    const float* Vb = g_V + (size_t)bh * S_ * HD_;

    for (int kt = 0; kt < S_; kt += TK) {
        // cooperative load of K/V tiles: TK*HD = 2048 floats = 512 float4 each
        const float4* ksrc = (const float4*)(Kb + (size_t)kt * HD_);
        const float4* vsrc = (const float4*)(Vb + (size_t)kt * HD_);
#pragma unroll
        for (int i = 0; i < 4; i++) {
            const int idx = tid + i * 128;
            ((float4*)Ks)[idx] = ksrc[idx];
            ((float4*)Vs)[idx] = vsrc[idx];
        }
        __syncthreads();

        float s[TK];
        float tmax = mrun;
#pragma unroll
        for (int j = 0; j < TK; j++) {
            const float4* kr = (const float4*)(Ks + j * HD_);
            float sum = 0.0f;
#pragma unroll
            for (int dd = 0; dd < 16; dd++) {
                float4 kv = kr[dd];
                sum += qr[dd * 4 + 0] * kv.x + qr[dd * 4 + 1] * kv.y
                     + qr[dd * 4 + 2] * kv.z + qr[dd * 4 + 3] * kv.w;
            }
            s[j] = sum * ATT_SCALE;
            tmax = fmaxf(tmax, s[j]);
        }

        const float corr = __expf(mrun - tmax);
        lrun *= corr;
#pragma unroll
        for (int d = 0; d < HD_; d++) acc[d] *= corr;

#pragma unroll
        for (int j = 0; j < TK; j++) {
            const float p = __expf(s[j] - tmax);
            lrun += p;
            const float4* vr = (const float4*)(Vs + j * HD_);
#pragma unroll
            for (int dd = 0; dd < 16; dd++) {
                float4 vv = vr[dd];
                acc[dd * 4 + 0] += p * vv.x;
                acc[dd * 4 + 1] += p * vv.y;
                acc[dd * 4 + 2] += p * vv.z;
                acc[dd * 4 + 3] += p * vv.w;
            }
        }
        mrun = tmax;
        __syncthreads();
    }

    const float inv = 1.0f / lrun;
    const int b_ = bh >> 4;       // bh / H
    const int h_ = bh & (H_ - 1);
    float* op = g_O + ((size_t)(b_ * S_ + q)) * DM_ + h_ * HD_;
#pragma unroll
    for (int i = 0; i < 16; i++) {
        float4 t;
        t.x = acc[4 * i + 0] * inv; t.y = acc[4 * i + 1] * inv;
        t.z = acc[4 * i + 2] * inv; t.w = acc[4 * i + 3] * inv;
        ((float4*)op)[i] = t;
    }
}

// ---------------------------------------------------------------------------
// Launch
// Inputs: 0 query, 1 key, 2 value, 3 Wq, 4 bq, 5 Wk, 6 bk, 7 Wv, 8 bv,
//         9 Wo, 10 bo
// ---------------------------------------------------------------------------
extern "C" void kernel_launch(void* const* d_in, const int* in_sizes, int n_in,
                              void* d_out, int out_size)
{
    const float* query = (const float*)d_in[0];
    const float* key   = (const float*)d_in[1];
    const float* value = (const float*)d_in[2];
    const float* Wq = (const float*)d_in[3];
    const float* bq = (const float*)d_in[4];
    const float* Wk = (const float*)d_in[5];
    const float* bk = (const float*)d_in[6];
    const float* Wv = (const float*)d_in[7];
    const float* bv = (const float*)d_in[8];
    const float* Wo = (const float*)d_in[9];
    const float* bo = (const float*)d_in[10];
    float* out = (float*)d_out;

    dim3 ggrid(DM_ / 128, MTOT / 128);   // (8, 32)
    gemm_kernel<1><<<ggrid, 256>>>(query, Wq, bq, nullptr);
    gemm_kernel<2><<<ggrid, 256>>>(key,   Wk, bk, nullptr);
    gemm_kernel<3><<<ggrid, 256>>>(value, Wv, bv, nullptr);

    attn_kernel<<<dim3(S_ / 128, B_ * H_), 128>>>();

    gemm_kernel<0><<<ggrid, 256>>>(nullptr, Wo, bo, out);
}

// round 4
// speedup vs baseline: 2.2605x; 2.2605x over previous
#include <cuda_runtime.h>
#include <cstdint>
#include <math.h>

#define B_ 2
#define S_ 2048
#define DM_ 1024
#define H_ 16
#define HD_ 64
#define MTOT (B_ * S_)      // 4096

#define fu __float_as_uint
#define uf __uint_as_float

// Scratch (allocation-free: __device__ globals)
__device__ float g_Q[(size_t)B_ * H_ * S_ * HD_];   // head-major [B,H,S,HD], tf32-rounded
__device__ float g_K[(size_t)B_ * H_ * S_ * HD_];
__device__ float g_V[(size_t)B_ * H_ * S_ * HD_];
__device__ float g_O[(size_t)B_ * S_ * DM_];        // row-major [B*S, DM], fp32

__device__ __forceinline__ uint32_t f2tf(float f) {
    uint32_t r;
    asm("cvt.rna.tf32.f32 %0, %1;" : "=r"(r) : "f"(f));
    return r;
}

__device__ __forceinline__ void mma_tf32(float c[4],
                                         uint32_t a0, uint32_t a1, uint32_t a2, uint32_t a3,
                                         uint32_t b0, uint32_t b1) {
    asm volatile(
        "mma.sync.aligned.m16n8k8.row.col.f32.tf32.tf32.f32 "
        "{%0,%1,%2,%3}, {%4,%5,%6,%7}, {%8,%9}, {%0,%1,%2,%3};\n"
        : "+f"(c[0]), "+f"(c[1]), "+f"(c[2]), "+f"(c[3])
        : "r"(a0), "r"(a1), "r"(a2), "r"(a3), "r"(b0), "r"(b1));
}

// ---------------------------------------------------------------------------
// tf32 GEMM: Y[m,n] = sum_k X[m,k]*W[n,k] + bias[n]
// MODE 0: X = g_O, Y = final output (fp32, row-major).
// MODE 1/2/3: X = input, Y = g_Q/g_K/g_V head-major, values tf32-rounded.
// Block 128x128, BK=32, 256 threads (8 warps, 2x4), warp tile 64x32.
// ---------------------------------------------------------------------------
template <int MODE>
__global__ __launch_bounds__(256, 2)
void gemm_tf32(const float* __restrict__ Xin, const float* __restrict__ W,
               const float* __restrict__ bias, float* __restrict__ Y)
{
    const float* X = (MODE == 0) ? (const float*)g_O : Xin;

    __shared__ float As[128][36];   // ld=36 => bank = (4*row + col) % 32
    __shared__ float Bs[128][36];

    const int tid  = threadIdx.x;
    const int warp = tid >> 5, lane = tid & 31;
    const int g  = lane >> 2, tg = lane & 3;
    const int wm = warp >> 2, wn = warp & 3;
    const int bm = blockIdx.y * 128, bn = blockIdx.x * 128;

    float acc[4][4][4];
#pragma unroll
    for (int i = 0; i < 4; i++)
#pragma unroll
        for (int j = 0; j < 4; j++)
#pragma unroll
            for (int k = 0; k < 4; k++) acc[i][j][k] = 0.0f;

    for (int k0 = 0; k0 < DM_; k0 += 32) {
#pragma unroll
        for (int i = 0; i < 4; i++) {
            const int f = tid + 256 * i;
            const int row = f >> 3;
            const int k4  = (f & 7) << 2;
            float4 x = *(const float4*)(X + (size_t)(bm + row) * DM_ + k0 + k4);
            float4 w = *(const float4*)(W + (size_t)(bn + row) * DM_ + k0 + k4);
            float4 xt, wt;
            xt.x = uf(f2tf(x.x)); xt.y = uf(f2tf(x.y));
            xt.z = uf(f2tf(x.z)); xt.w = uf(f2tf(x.w));
            wt.x = uf(f2tf(w.x)); wt.y = uf(f2tf(w.y));
            wt.z = uf(f2tf(w.z)); wt.w = uf(f2tf(w.w));
            *(float4*)&As[row][k4] = xt;
            *(float4*)&Bs[row][k4] = wt;
        }
        __syncthreads();

#pragma unroll
        for (int ks = 0; ks < 4; ks++) {
            const int kk = ks * 8;
            uint32_t af[4][4], bf[4][2];
#pragma unroll
            for (int mi = 0; mi < 4; mi++) {
                const int r = wm * 64 + mi * 16 + g;
                af[mi][0] = fu(As[r][kk + tg]);
                af[mi][1] = fu(As[r + 8][kk + tg]);
                af[mi][2] = fu(As[r][kk + tg + 4]);
                af[mi][3] = fu(As[r + 8][kk + tg + 4]);
            }
#pragma unroll
            for (int ni = 0; ni < 4; ni++) {
                const int c = wn * 32 + ni * 8 + g;
                bf[ni][0] = fu(Bs[c][kk + tg]);
                bf[ni][1] = fu(Bs[c][kk + tg + 4]);
            }
#pragma unroll
            for (int mi = 0; mi < 4; mi++)
#pragma unroll
                for (int ni = 0; ni < 4; ni++)
                    mma_tf32(acc[mi][ni], af[mi][0], af[mi][1], af[mi][2], af[mi][3],
                             bf[ni][0], bf[ni][1]);
        }
        __syncthreads();
    }

    // epilogue
#pragma unroll
    for (int mi = 0; mi < 4; mi++) {
#pragma unroll
        for (int ni = 0; ni < 4; ni++) {
            const int m = bm + wm * 64 + mi * 16 + g;
            const int n = bn + wn * 32 + ni * 8 + 2 * tg;
            const float b0 = bias[n], b1 = bias[n + 1];
            float v00 = acc[mi][ni][0] + b0;
            float v01 = acc[mi][ni][1] + b1;
            float v10 = acc[mi][ni][2] + b0;
            float v11 = acc[mi][ni][3] + b1;
            if (MODE == 0) {
                *(float2*)(Y + (size_t)m * DM_ + n)       = make_float2(v00, v01);
                *(float2*)(Y + (size_t)(m + 8) * DM_ + n) = make_float2(v10, v11);
            } else {
                // pre-round to tf32 so attention skips cvt
                v00 = uf(f2tf(v00)); v01 = uf(f2tf(v01));
                v10 = uf(f2tf(v10)); v11 = uf(f2tf(v11));
                float* dst = (MODE == 1) ? g_Q : (MODE == 2) ? g_K : g_V;
                const int h_ = n >> 6, d_ = n & (HD_ - 1);
                {
                    const int b_ = m >> 11, s_ = m & (S_ - 1);
                    *(float2*)(dst + (((size_t)b_ * H_ + h_) * S_ + s_) * HD_ + d_) =
                        make_float2(v00, v01);
                }
                {
                    const int m2 = m + 8;
                    const int b_ = m2 >> 11, s_ = m2 & (S_ - 1);
                    *(float2*)(dst + (((size_t)b_ * H_ + h_) * S_ + s_) * HD_ + d_) =
                        make_float2(v10, v11);
                }
            }
        }
    }
}

// ---------------------------------------------------------------------------
// Flash attention with softmax-one, tf32 mma.
// Block: 256 threads (8 warps), Br=128 q rows (16 per warp), Bc=64.
// O computed transposed: O^T = V^T @ P^T (so P's C-frag layout feeds B-frags
// via an SMEM round-trip with zero cross-warp traffic).
// Dynamic SMEM: Qs[128][68] (reused as Ps), Ks[64][68], Vs[64][72].
// ---------------------------------------------------------------------------
#define QS_LD 68
#define KS_LD 68
#define VS_LD 72

__global__ __launch_bounds__(256, 1)
void attn_tf32()
{
    extern __shared__ float sm[];
    float* Qs = sm;                               // 128*68 (also Ps)
    float* Ks = sm + 128 * QS_LD;                 // 64*68
    float* Vs = sm + 128 * QS_LD + 64 * KS_LD;    // 64*72

    const int tid  = threadIdx.x;
    const int warp = tid >> 5, lane = tid & 31;
    const int g = lane >> 2, tg = lane & 3;
    const int bh = blockIdx.y;
    const int q0blk = blockIdx.x * 128;
    const int b = bh >> 4, h = bh & (H_ - 1);

    const float* Qg = g_Q + ((size_t)bh * S_ + q0blk) * HD_;
    const float* Kg = g_K + (size_t)bh * S_ * HD_;
    const float* Vg = g_V + (size_t)bh * S_ * HD_;

    // stage Q tile (128x64) then extract fragments (scale folded in: *0.125 exact)
#pragma unroll
    for (int i = 0; i < 8; i++) {
        const int f = tid + 256 * i;
        const int row = f >> 4, d4 = (f & 15) << 2;
        float4 qv = *(const float4*)(Qg + (size_t)row * HD_ + d4);
        *(float4*)&Qs[row * QS_LD + d4] = qv;
    }
    __syncthreads();

    uint32_t qf[8][4];
    const int qrow = warp * 16 + g;
#pragma unroll
    for (int ks = 0; ks < 8; ks++) {
        const int d = ks * 8 + tg;
        qf[ks][0] = fu(0.125f * Qs[qrow * QS_LD + d]);
        qf[ks][1] = fu(0.125f * Qs[(qrow + 8) * QS_LD + d]);
        qf[ks][2] = fu(0.125f * Qs[qrow * QS_LD + d + 4]);
        qf[ks][3] = fu(0.125f * Qs[(qrow + 8) * QS_LD + d + 4]);
    }
    __syncthreads();   // Qs now reusable as Ps

    float oacc[4][2][4];
#pragma unroll
    for (int i = 0; i < 4; i++)
#pragma unroll
        for (int j = 0; j < 2; j++)
#pragma unroll
            for (int k = 0; k < 4; k++) oacc[i][j][k] = 0.0f;

    float m0 = 0.0f, m1 = 0.0f;   // virtual zero logit
    float l0 = 1.0f, l1 = 1.0f;

    for (int kt = 0; kt < S_; kt += 64) {
        // G2S: K and V tiles (64x64 each)
#pragma unroll
        for (int i = 0; i < 4; i++) {
            const int f = tid + 256 * i;
            const int row = f >> 4, d4 = (f & 15) << 2;
            float4 kv = *(const float4*)(Kg + (size_t)(kt + row) * HD_ + d4);
            float4 vv = *(const float4*)(Vg + (size_t)(kt + row) * HD_ + d4);
            *(float4*)&Ks[row * KS_LD + d4] = kv;
            *(float4*)&Vs[row * VS_LD + d4] = vv;
        }
        __syncthreads();

        // S = Q @ K^T : per warp 16x64, 8 kc-tiles x 8 d-steps
        float s[8][4];
#pragma unroll
        for (int nt = 0; nt < 8; nt++) {
            s[nt][0] = s[nt][1] = s[nt][2] = s[nt][3] = 0.0f;
#pragma unroll
            for (int ks = 0; ks < 8; ks++) {
                const uint32_t b0 = fu(Ks[(nt * 8 + g) * KS_LD + ks * 8 + tg]);
                const uint32_t b1 = fu(Ks[(nt * 8 + g) * KS_LD + ks * 8 + tg + 4]);
                mma_tf32(s[nt], qf[ks][0], qf[ks][1], qf[ks][2], qf[ks][3], b0, b1);
            }
        }

        // online softmax-one (rows r0 = qrow, r1 = qrow+8)
        float rm0 = m0, rm1 = m1;
#pragma unroll
        for (int nt = 0; nt < 8; nt++) {
            rm0 = fmaxf(rm0, fmaxf(s[nt][0], s[nt][1]));
            rm1 = fmaxf(rm1, fmaxf(s[nt][2], s[nt][3]));
        }
        rm0 = fmaxf(rm0, __shfl_xor_sync(0xffffffffu, rm0, 1));
        rm0 = fmaxf(rm0, __shfl_xor_sync(0xffffffffu, rm0, 2));
        rm1 = fmaxf(rm1, __shfl_xor_sync(0xffffffffu, rm1, 1));
        rm1 = fmaxf(rm1, __shfl_xor_sync(0xffffffffu, rm1, 2));

        const float corr0 = __expf(m0 - rm0);
        const float corr1 = __expf(m1 - rm1);

        float ls0 = 0.0f, ls1 = 0.0f;
#pragma unroll
        for (int nt = 0; nt < 8; nt++) {
            const float p00 = __expf(s[nt][0] - rm0);
            const float p01 = __expf(s[nt][1] - rm0);
            const float p10 = __expf(s[nt][2] - rm1);
            const float p11 = __expf(s[nt][3] - rm1);
            ls0 += p00 + p01;
            ls1 += p10 + p11;
            const int col = nt * 8 + 2 * tg;
            Qs[qrow * QS_LD + col]           = uf(f2tf(p00));
            Qs[qrow * QS_LD + col + 1]       = uf(f2tf(p01));
            Qs[(qrow + 8) * QS_LD + col]     = uf(f2tf(p10));
            Qs[(qrow + 8) * QS_LD + col + 1] = uf(f2tf(p11));
        }
        ls0 += __shfl_xor_sync(0xffffffffu, ls0, 1);
        ls0 += __shfl_xor_sync(0xffffffffu, ls0, 2);
        ls1 += __shfl_xor_sync(0xffffffffu, ls1, 1);
        ls1 += __shfl_xor_sync(0xffffffffu, ls1, 2);
        l0 = l0 * corr0 + ls0; m0 = rm0;
        l1 = l1 * corr1 + ls1; m1 = rm1;
        __syncwarp();

        // rescale O^T accumulators: need corr per q-column via shuffle
#pragma unroll
        for (int nt = 0; nt < 2; nt++) {
            const int ql0 = 2 * tg, ql1 = 2 * tg + 1;
            float c0a = __shfl_sync(0xffffffffu, corr0, ql0 * 4);
            float c0b = __shfl_sync(0xffffffffu, corr1, ql0 * 4);
            float c1a = __shfl_sync(0xffffffffu, corr0, ql1 * 4);
            float c1b = __shfl_sync(0xffffffffu, corr1, ql1 * 4);
            const float cq0 = (nt == 0) ? c0a : c0b;
            const float cq1 = (nt == 0) ? c1a : c1b;
#pragma unroll
            for (int dt = 0; dt < 4; dt++) {
                oacc[dt][nt][0] *= cq0;
                oacc[dt][nt][1] *= cq1;
                oacc[dt][nt][2] *= cq0;
                oacc[dt][nt][3] *= cq1;
            }
        }

        // O^T += V^T @ P^T : A-frags from Vs (untransposed, ld=72), B-frags from Ps
#pragma unroll
        for (int ks = 0; ks < 8; ks++) {
            uint32_t pb[2][2];
            pb[0][0] = fu(Qs[(warp * 16 + g) * QS_LD + ks * 8 + tg]);
            pb[0][1] = fu(Qs[(warp * 16 + g) * QS_LD + ks * 8 + tg + 4]);
            pb[1][0] = fu(Qs[(warp * 16 + 8 + g) * QS_LD + ks * 8 + tg]);
            pb[1][1] = fu(Qs[(warp * 16 + 8 + g) * QS_LD + ks * 8 + tg + 4]);
#pragma unroll
            for (int dt = 0; dt < 4; dt++) {
                const uint32_t a0 = fu(Vs[(ks * 8 + tg) * VS_LD + dt * 16 + g]);
                const uint32_t a1 = fu(Vs[(ks * 8 + tg) * VS_LD + dt * 16 + g + 8]);
                const uint32_t a2 = fu(Vs[(ks * 8 + tg + 4) * VS_LD + dt * 16 + g]);
                const uint32_t a3 = fu(Vs[(ks * 8 + tg + 4) * VS_LD + dt * 16 + g + 8]);
                mma_tf32(oacc[dt][0], a0, a1, a2, a3, pb[0][0], pb[0][1]);
                mma_tf32(oacc[dt][1], a0, a1, a2, a3, pb[1][0], pb[1][1]);
            }
        }
        __syncthreads();
    }

    // finalize: divide by l (per q-row), store O^T frags to g_O
    const float inv0 = 1.0f / l0;
    const float inv1 = 1.0f / l1;
    float ivq[2][2];
#pragma unroll
    for (int nt = 0; nt < 2; nt++) {
        const int ql0 = 2 * tg, ql1 = 2 * tg + 1;
        float a0 = __shfl_sync(0xffffffffu, inv0, ql0 * 4);
        float b0 = __shfl_sync(0xffffffffu, inv1, ql0 * 4);
        float a1 = __shfl_sync(0xffffffffu, inv0, ql1 * 4);
        float b1 = __shfl_sync(0xffffffffu, inv1, ql1 * 4);
        ivq[nt][0] = (nt == 0) ? a0 : b0;
        ivq[nt][1] = (nt == 0) ? a1 : b1;
    }

    const size_t obase = ((size_t)(b * S_ + q0blk + warp * 16)) * DM_ + h * HD_;
#pragma unroll
    for (int dt = 0; dt < 4; dt++) {
#pragma unroll
        for (int nt = 0; nt < 2; nt++) {
            const int d  = dt * 16 + g;
            const int ql = nt * 8 + 2 * tg;
            g_O[obase + (size_t)ql * DM_ + d]           = oacc[dt][nt][0] * ivq[nt][0];
            g_O[obase + (size_t)(ql + 1) * DM_ + d]     = oacc[dt][nt][1] * ivq[nt][1];
            g_O[obase + (size_t)ql * DM_ + d + 8]       = oacc[dt][nt][2] * ivq[nt][0];
            g_O[obase + (size_t)(ql + 1) * DM_ + d + 8] = oacc[dt][nt][3] * ivq[nt][1];
        }
    }
}

// ---------------------------------------------------------------------------
// Launch
// ---------------------------------------------------------------------------
extern "C" void kernel_launch(void* const* d_in, const int* in_sizes, int n_in,
                              void* d_out, int out_size)
{
    const float* query = (const float*)d_in[0];
    const float* key   = (const float*)d_in[1];
    const float* value = (const float*)d_in[2];
    const float* Wq = (const float*)d_in[3];
    const float* bq = (const float*)d_in[4];
    const float* Wk = (const float*)d_in[5];
    const float* bk = (const float*)d_in[6];
    const float* Wv = (const float*)d_in[7];
    const float* bv = (const float*)d_in[8];
    const float* Wo = (const float*)d_in[9];
    const float* bo = (const float*)d_in[10];
    float* out = (float*)d_out;

    const int attn_smem = (128 * QS_LD + 64 * KS_LD + 64 * VS_LD) * 4;
    cudaFuncSetAttribute(attn_tf32, cudaFuncAttributeMaxDynamicSharedMemorySize, attn_smem);

    dim3 ggrid(DM_ / 128, MTOT / 128);   // (8, 32)
    gemm_tf32<1><<<ggrid, 256>>>(query, Wq, bq, nullptr);
    gemm_tf32<2><<<ggrid, 256>>>(key,   Wk, bk, nullptr);
    gemm_tf32<3><<<ggrid, 256>>>(value, Wv, bv, nullptr);

    attn_tf32<<<dim3(S_ / 128, B_ * H_), 256, attn_smem>>>();

    gemm_tf32<0><<<ggrid, 256>>>(nullptr, Wo, bo, out);
}

// round 7
// speedup vs baseline: 3.9090x; 1.7293x over previous
#include <cuda_runtime.h>
#include <cstdint>
#include <math.h>

#define B_ 2
#define S_ 2048
#define DM_ 1024
#define H_ 16
#define HD_ 64
#define MTOT (B_ * S_)      // 4096

#define fu __float_as_uint
#define uf __uint_as_float

// Scratch (allocation-free: __device__ globals; referenced ONLY in device code)
__device__ float g_Q[(size_t)B_ * H_ * S_ * HD_];   // head-major [B,H,S,HD], tf32-rounded
__device__ float g_K[(size_t)B_ * H_ * S_ * HD_];
__device__ float g_V[(size_t)B_ * H_ * S_ * HD_];
__device__ float g_O[(size_t)B_ * S_ * DM_];        // row-major [B*S,DM], tf32-rounded
__device__ float g_Xq[(size_t)MTOT * DM_];          // tf32-rounded inputs
__device__ float g_Xk[(size_t)MTOT * DM_];
__device__ float g_Xv[(size_t)MTOT * DM_];
__device__ float g_Wq[(size_t)DM_ * DM_];           // tf32-rounded weights
__device__ float g_Wk[(size_t)DM_ * DM_];
__device__ float g_Wv[(size_t)DM_ * DM_];
__device__ float g_Wo[(size_t)DM_ * DM_];

__device__ __forceinline__ uint32_t f2tf(float f) {
    uint32_t r;
    asm("cvt.rna.tf32.f32 %0, %1;" : "=r"(r) : "f"(f));
    return r;
}

__device__ __forceinline__ void mma_tf32(float c[4],
                                         uint32_t a0, uint32_t a1, uint32_t a2, uint32_t a3,
                                         uint32_t b0, uint32_t b1) {
    asm volatile(
        "mma.sync.aligned.m16n8k8.row.col.f32.tf32.tf32.f32 "
        "{%0,%1,%2,%3}, {%4,%5,%6,%7}, {%8,%9}, {%0,%1,%2,%3};\n"
        : "+f"(c[0]), "+f"(c[1]), "+f"(c[2]), "+f"(c[3])
        : "r"(a0), "r"(a1), "r"(a2), "r"(a3), "r"(b0), "r"(b1));
}

__device__ __forceinline__ void cpa16(uint32_t dst, const void* src) {
    asm volatile("cp.async.cg.shared.global [%0], [%1], 16;" :: "r"(dst), "l"(src));
}
#define CP_COMMIT() asm volatile("cp.async.commit_group;")
#define CP_WAIT1()  asm volatile("cp.async.wait_group 1;")

// ---------------------------------------------------------------------------
// Prep: round inputs and weights to tf32 (RNA) once (elementwise, exact).
// Globals written from device code (device symbols never passed from host).
// ---------------------------------------------------------------------------
__global__ void prep_round(const float* __restrict__ q, const float* __restrict__ k,
                           const float* __restrict__ v, const float* __restrict__ wq,
                           const float* __restrict__ wk, const float* __restrict__ wv,
                           const float* __restrict__ wo)
{
    const float* src; float* dst; int n;
    switch (blockIdx.y) {
        case 0: src = q;  dst = g_Xq; n = MTOT * DM_; break;
        case 1: src = k;  dst = g_Xk; n = MTOT * DM_; break;
        case 2: src = v;  dst = g_Xv; n = MTOT * DM_; break;
        case 3: src = wq; dst = g_Wq; n = DM_ * DM_;  break;
        case 4: src = wk; dst = g_Wk; n = DM_ * DM_;  break;
        case 5: src = wv; dst = g_Wv; n = DM_ * DM_;  break;
        default: src = wo; dst = g_Wo; n = DM_ * DM_; break;
    }
    const int n4 = n >> 2;
    for (int i = blockIdx.x * blockDim.x + threadIdx.x; i < n4;
         i += gridDim.x * blockDim.x) {
        float4 x = ((const float4*)src)[i];
        x.x = uf(f2tf(x.x)); x.y = uf(f2tf(x.y));
        x.z = uf(f2tf(x.z)); x.w = uf(f2tf(x.w));
        ((float4*)dst)[i] = x;
    }
}

// ---------------------------------------------------------------------------
// tf32 GEMM (cp.async double-buffered): Y[m,n] = sum_k X[m,k]*W[n,k] + bias[n]
// X and W chosen from device globals INSIDE the kernel (MODE).
// MODE 0: X=g_O,  W=g_Wo -> Y = final output (param).
// MODE 1: X=g_Xq, W=g_Wq -> g_Q; MODE 2: g_Xk/g_Wk -> g_K; MODE 3: -> g_V.
// Block 128x128, BK=32, 256 threads, occ 2.
// ---------------------------------------------------------------------------
#define GTILE (128 * 36)

template <int MODE>
__global__ __launch_bounds__(256, 2)
void gemm_tf32(const float* __restrict__ bias, float* __restrict__ Y)
{
    const float* X = (MODE == 0) ? g_O : (MODE == 1) ? g_Xq : (MODE == 2) ? g_Xk : g_Xv;
    const float* W = (MODE == 0) ? g_Wo : (MODE == 1) ? g_Wq : (MODE == 2) ? g_Wk : g_Wv;

    extern __shared__ float smg[];
    float* As = smg;              // [2][128][36]
    float* Bs = smg + 2 * GTILE;  // [2][128][36]
    const uint32_t sA = (uint32_t)__cvta_generic_to_shared(As);
    const uint32_t sB = (uint32_t)__cvta_generic_to_shared(Bs);

    const int tid  = threadIdx.x;
    const int warp = tid >> 5, lane = tid & 31;
    const int g  = lane >> 2, tg = lane & 3;
    const int wm = warp >> 2, wn = warp & 3;
    const int bm = blockIdx.y * 128, bn = blockIdx.x * 128;

    float acc[4][4][4];
#pragma unroll
    for (int i = 0; i < 4; i++)
#pragma unroll
        for (int j = 0; j < 4; j++)
#pragma unroll
            for (int k = 0; k < 4; k++) acc[i][j][k] = 0.0f;

    const int lrow = tid >> 3;          // 0..31 -> row base
    const int lc4  = (tid & 7) << 2;    // 0..28

    // prefetch tile 0
#pragma unroll
    for (int i = 0; i < 4; i++) {
        const int row = lrow + 32 * i;
        const uint32_t off = (uint32_t)(row * 36 + lc4) << 2;
        cpa16(sA + off, X + (size_t)(bm + row) * DM_ + lc4);
        cpa16(sB + off, W + (size_t)(bn + row) * DM_ + lc4);
    }
    CP_COMMIT();

    for (int t = 0; t < 32; t++) {
        if (t + 1 < 32) {
            const int k0 = (t + 1) * 32;
            const uint32_t bufo = (uint32_t)(((t + 1) & 1) * GTILE) << 2;
#pragma unroll
            for (int i = 0; i < 4; i++) {
                const int row = lrow + 32 * i;
                const uint32_t off = bufo + ((uint32_t)(row * 36 + lc4) << 2);
                cpa16(sA + off, X + (size_t)(bm + row) * DM_ + k0 + lc4);
                cpa16(sB + off, W + (size_t)(bn + row) * DM_ + k0 + lc4);
            }
        }
        CP_COMMIT();
        CP_WAIT1();
        __syncthreads();

        const float* Ab = As + (t & 1) * GTILE;
        const float* Bb = Bs + (t & 1) * GTILE;
#pragma unroll
        for (int ks = 0; ks < 4; ks++) {
            const int kk = ks * 8;
            uint32_t af[4][4], bf[4][2];
#pragma unroll
            for (int mi = 0; mi < 4; mi++) {
                const int r = wm * 64 + mi * 16 + g;
                af[mi][0] = fu(Ab[r * 36 + kk + tg]);
                af[mi][1] = fu(Ab[(r + 8) * 36 + kk + tg]);
                af[mi][2] = fu(Ab[r * 36 + kk + tg + 4]);
                af[mi][3] = fu(Ab[(r + 8) * 36 + kk + tg + 4]);
            }
#pragma unroll
            for (int ni = 0; ni < 4; ni++) {
                const int c = wn * 32 + ni * 8 + g;
                bf[ni][0] = fu(Bb[c * 36 + kk + tg]);
                bf[ni][1] = fu(Bb[c * 36 + kk + tg + 4]);
            }
#pragma unroll
            for (int mi = 0; mi < 4; mi++)
#pragma unroll
                for (int ni = 0; ni < 4; ni++)
                    mma_tf32(acc[mi][ni], af[mi][0], af[mi][1], af[mi][2], af[mi][3],
                             bf[ni][0], bf[ni][1]);
        }
        __syncthreads();
    }

    // epilogue
#pragma unroll
    for (int mi = 0; mi < 4; mi++) {
#pragma unroll
        for (int ni = 0; ni < 4; ni++) {
            const int m = bm + wm * 64 + mi * 16 + g;
            const int n = bn + wn * 32 + ni * 8 + 2 * tg;
            const float b0 = bias[n], b1 = bias[n + 1];
            float v00 = acc[mi][ni][0] + b0;
            float v01 = acc[mi][ni][1] + b1;
            float v10 = acc[mi][ni][2] + b0;
            float v11 = acc[mi][ni][3] + b1;
            if (MODE == 0) {
                *(float2*)(Y + (size_t)m * DM_ + n)       = make_float2(v00, v01);
                *(float2*)(Y + (size_t)(m + 8) * DM_ + n) = make_float2(v10, v11);
            } else {
                v00 = uf(f2tf(v00)); v01 = uf(f2tf(v01));
                v10 = uf(f2tf(v10)); v11 = uf(f2tf(v11));
                float* dst = (MODE == 1) ? g_Q : (MODE == 2) ? g_K : g_V;
                const int h_ = n >> 6, d_ = n & (HD_ - 1);
                {
                    const int b_ = m >> 11, s_ = m & (S_ - 1);
                    *(float2*)(dst + (((size_t)b_ * H_ + h_) * S_ + s_) * HD_ + d_) =
                        make_float2(v00, v01);
                }
                {
                    const int m2 = m + 8;
                    const int b_ = m2 >> 11, s_ = m2 & (S_ - 1);
                    *(float2*)(dst + (((size_t)b_ * H_ + h_) * S_ + s_) * HD_ + d_) =
                        make_float2(v10, v11);
                }
            }
        }
    }
}

// ---------------------------------------------------------------------------
// Flash attention, softmax-one, tf32 mma, cp.async double-buffered K/V, occ 2.
// 256 threads, Br=128 (16 q rows/warp), Bc=64 as two 32-col chunks (score regs
// 16 -> fits 128-reg budget). O computed transposed (O^T = V^T @ P^T).
// ---------------------------------------------------------------------------
#define QS_LD 68
#define KS_LD 68
#define VS_LD 72
#define KTILE (64 * KS_LD)
#define VTILE (64 * VS_LD)

__global__ __launch_bounds__(256, 2)
void attn_tf32()
{
    extern __shared__ float sm[];
    float* Qs = sm;                       // 128*68 (reused as Ps)
    float* Ks = sm + 128 * QS_LD;         // [2][64][68]
    float* Vs = Ks + 2 * KTILE;           // [2][64][72]
    const uint32_t sK = (uint32_t)__cvta_generic_to_shared(Ks);
    const uint32_t sV = (uint32_t)__cvta_generic_to_shared(Vs);

    const int tid  = threadIdx.x;
    const int warp = tid >> 5, lane = tid & 31;
    const int g = lane >> 2, tg = lane & 3;
    const int bh = blockIdx.y;
    const int q0blk = blockIdx.x * 128;
    const int b = bh >> 4, h = bh & (H_ - 1);

    const float* Qg = g_Q + ((size_t)bh * S_ + q0blk) * HD_;
    const float* Kg = g_K + (size_t)bh * S_ * HD_;
    const float* Vg = g_V + (size_t)bh * S_ * HD_;

    const int lrow16 = tid >> 4;          // 0..15
    const int lc4    = (tid & 15) << 2;   // 0..60

    // prefetch K/V tile 0
#pragma unroll
    for (int i = 0; i < 4; i++) {
        const int row = lrow16 + 16 * i;
        cpa16(sK + ((uint32_t)(row * KS_LD + lc4) << 2), Kg + (size_t)row * HD_ + lc4);
        cpa16(sV + ((uint32_t)(row * VS_LD + lc4) << 2), Vg + (size_t)row * HD_ + lc4);
    }
    CP_COMMIT();

    // stage Q tile, extract fragments (0.125 scale exact in tf32)
#pragma unroll
    for (int i = 0; i < 8; i++) {
        const int f = tid + 256 * i;
        const int row = f >> 4, d4 = (f & 15) << 2;
        *(float4*)&Qs[row * QS_LD + d4] = *(const float4*)(Qg + (size_t)row * HD_ + d4);
    }
    __syncthreads();

    uint32_t qf[8][4];
    const int qrow = warp * 16 + g;
#pragma unroll
    for (int ks = 0; ks < 8; ks++) {
        const int d = ks * 8 + tg;
        qf[ks][0] = fu(0.125f * Qs[qrow * QS_LD + d]);
        qf[ks][1] = fu(0.125f * Qs[(qrow + 8) * QS_LD + d]);
        qf[ks][2] = fu(0.125f * Qs[qrow * QS_LD + d + 4]);
        qf[ks][3] = fu(0.125f * Qs[(qrow + 8) * QS_LD + d + 4]);
    }
    __syncthreads();   // Qs now reusable as Ps

    float oacc[4][2][4];
#pragma unroll
    for (int i = 0; i < 4; i++)
#pragma unroll
        for (int j = 0; j < 2; j++)
#pragma unroll
            for (int k = 0; k < 4; k++) oacc[i][j][k] = 0.0f;

    float m0 = 0.0f, m1 = 0.0f;   // virtual zero logit
    float l0 = 1.0f, l1 = 1.0f;

    for (int t = 0; t < 32; t++) {
        if (t + 1 < 32) {
            const size_t gofs = (size_t)(t + 1) * 64;
            const uint32_t bK = (uint32_t)(((t + 1) & 1) * KTILE) << 2;
            const uint32_t bV = (uint32_t)(((t + 1) & 1) * VTILE) << 2;
#pragma unroll
            for (int i = 0; i < 4; i++) {
                const int row = lrow16 + 16 * i;
                cpa16(sK + bK + ((uint32_t)(row * KS_LD + lc4) << 2),
                      Kg + (gofs + row) * HD_ + lc4);
                cpa16(sV + bV + ((uint32_t)(row * VS_LD + lc4) << 2),
                      Vg + (gofs + row) * HD_ + lc4);
            }
        }
        CP_COMMIT();
        CP_WAIT1();
        __syncthreads();

        const float* Ksb = Ks + (t & 1) * KTILE;
        const float* Vsb = Vs + (t & 1) * VTILE;

#pragma unroll
        for (int c = 0; c < 2; c++) {
            const int colbase = c * 32;
            float s[4][4];
#pragma unroll
            for (int nt = 0; nt < 4; nt++) {
                s[nt][0] = s[nt][1] = s[nt][2] = s[nt][3] = 0.0f;
#pragma unroll
                for (int ks = 0; ks < 8; ks++) {
                    const uint32_t b0 = fu(Ksb[(colbase + nt * 8 + g) * KS_LD + ks * 8 + tg]);
                    const uint32_t b1 = fu(Ksb[(colbase + nt * 8 + g) * KS_LD + ks * 8 + tg + 4]);
                    mma_tf32(s[nt], qf[ks][0], qf[ks][1], qf[ks][2], qf[ks][3], b0, b1);
                }
            }

            // online softmax-one update (chunk composes with running m/l)
            float rm0 = m0, rm1 = m1;
#pragma unroll
            for (int nt = 0; nt < 4; nt++) {
                rm0 = fmaxf(rm0, fmaxf(s[nt][0], s[nt][1]));
                rm1 = fmaxf(rm1, fmaxf(s[nt][2], s[nt][3]));
            }
            rm0 = fmaxf(rm0, __shfl_xor_sync(0xffffffffu, rm0, 1));
            rm0 = fmaxf(rm0, __shfl_xor_sync(0xffffffffu, rm0, 2));
            rm1 = fmaxf(rm1, __shfl_xor_sync(0xffffffffu, rm1, 1));
            rm1 = fmaxf(rm1, __shfl_xor_sync(0xffffffffu, rm1, 2));

            const float corr0 = __expf(m0 - rm0);
            const float corr1 = __expf(m1 - rm1);

            float ls0 = 0.0f, ls1 = 0.0f;
#pragma unroll
            for (int nt = 0; nt < 4; nt++) {
                const float p00 = __expf(s[nt][0] - rm0);
                const float p01 = __expf(s[nt][1] - rm0);
                const float p10 = __expf(s[nt][2] - rm1);
                const float p11 = __expf(s[nt][3] - rm1);
                ls0 += p00 + p01;
                ls1 += p10 + p11;
                const int col = colbase + nt * 8 + 2 * tg;
                Qs[qrow * QS_LD + col]           = uf(f2tf(p00));
                Qs[qrow * QS_LD + col + 1]       = uf(f2tf(p01));
                Qs[(qrow + 8) * QS_LD + col]     = uf(f2tf(p10));
                Qs[(qrow + 8) * QS_LD + col + 1] = uf(f2tf(p11));
            }
            ls0 += __shfl_xor_sync(0xffffffffu, ls0, 1);
            ls0 += __shfl_xor_sync(0xffffffffu, ls0, 2);
            ls1 += __shfl_xor_sync(0xffffffffu, ls1, 1);
            ls1 += __shfl_xor_sync(0xffffffffu, ls1, 2);
            l0 = l0 * corr0 + ls0; m0 = rm0;
            l1 = l1 * corr1 + ls1; m1 = rm1;
            __syncwarp();

            // rescale O^T accumulators (corr per q-column via shuffle)
#pragma unroll
            for (int nt = 0; nt < 2; nt++) {
                const int ql0 = 2 * tg, ql1 = 2 * tg + 1;
                float c0a = __shfl_sync(0xffffffffu, corr0, ql0 * 4);
                float c0b = __shfl_sync(0xffffffffu, corr1, ql0 * 4);
                float c1a = __shfl_sync(0xffffffffu, corr0, ql1 * 4);
                float c1b = __shfl_sync(0xffffffffu, corr1, ql1 * 4);
                const float cq0 = (nt == 0) ? c0a : c0b;
                const float cq1 = (nt == 0) ? c1a : c1b;
#pragma unroll
                for (int dt = 0; dt < 4; dt++) {
                    oacc[dt][nt][0] *= cq0;
                    oacc[dt][nt][1] *= cq1;
                    oacc[dt][nt][2] *= cq0;
                    oacc[dt][nt][3] *= cq1;
                }
            }

            // O^T += V^T @ P^T for this 32-wide chunk
#pragma unroll
            for (int ks2 = 0; ks2 < 4; ks2++) {
                const int kk = colbase + ks2 * 8;
                uint32_t pb[2][2];
                pb[0][0] = fu(Qs[(warp * 16 + g) * QS_LD + kk + tg]);
                pb[0][1] = fu(Qs[(warp * 16 + g) * QS_LD + kk + tg + 4]);
                pb[1][0] = fu(Qs[(warp * 16 + 8 + g) * QS_LD + kk + tg]);
                pb[1][1] = fu(Qs[(warp * 16 + 8 + g) * QS_LD + kk + tg + 4]);
#pragma unroll
                for (int dt = 0; dt < 4; dt++) {
                    const uint32_t a0 = fu(Vsb[(kk + tg) * VS_LD + dt * 16 + g]);
                    const uint32_t a1 = fu(Vsb[(kk + tg) * VS_LD + dt * 16 + g + 8]);
                    const uint32_t a2 = fu(Vsb[(kk + tg + 4) * VS_LD + dt * 16 + g]);
                    const uint32_t a3 = fu(Vsb[(kk + tg + 4) * VS_LD + dt * 16 + g + 8]);
                    mma_tf32(oacc[dt][0], a0, a1, a2, a3, pb[0][0], pb[0][1]);
                    mma_tf32(oacc[dt][1], a0, a1, a2, a3, pb[1][0], pb[1][1]);
                }
            }
        }
        __syncthreads();
    }

    // finalize: divide by l (per q-row), tf32-round, store O^T frags to g_O
    const float inv0 = 1.0f / l0;
    const float inv1 = 1.0f / l1;
    float ivq[2][2];
#pragma unroll
    for (int nt = 0; nt < 2; nt++) {
        const int ql0 = 2 * tg, ql1 = 2 * tg + 1;
        float a0 = __shfl_sync(0xffffffffu, inv0, ql0 * 4);
        float b0 = __shfl_sync(0xffffffffu, inv1, ql0 * 4);
        float a1 = __shfl_sync(0xffffffffu, inv0, ql1 * 4);
        float b1 = __shfl_sync(0xffffffffu, inv1, ql1 * 4);
        ivq[nt][0] = (nt == 0) ? a0 : b0;
        ivq[nt][1] = (nt == 0) ? a1 : b1;
    }

    const size_t obase = ((size_t)(b * S_ + q0blk + warp * 16)) * DM_ + h * HD_;
#pragma unroll
    for (int dt = 0; dt < 4; dt++) {
#pragma unroll
        for (int nt = 0; nt < 2; nt++) {
            const int d  = dt * 16 + g;
            const int ql = nt * 8 + 2 * tg;
            g_O[obase + (size_t)ql * DM_ + d]           = uf(f2tf(oacc[dt][nt][0] * ivq[nt][0]));
            g_O[obase + (size_t)(ql + 1) * DM_ + d]     = uf(f2tf(oacc[dt][nt][1] * ivq[nt][1]));
            g_O[obase + (size_t)ql * DM_ + d + 8]       = uf(f2tf(oacc[dt][nt][2] * ivq[nt][0]));
            g_O[obase + (size_t)(ql + 1) * DM_ + d + 8] = uf(f2tf(oacc[dt][nt][3] * ivq[nt][1]));
        }
    }
}

// ---------------------------------------------------------------------------
// Launch (only harness pointers cross the host/device boundary)
// ---------------------------------------------------------------------------
extern "C" void kernel_launch(void* const* d_in, const int* in_sizes, int n_in,
                              void* d_out, int out_size)
{
    const float* query = (const float*)d_in[0];
    const float* key   = (const float*)d_in[1];
    const float* value = (const float*)d_in[2];
    const float* bq = (const float*)d_in[4];
    const float* bk = (const float*)d_in[6];
    const float* bv = (const float*)d_in[8];
    const float* bo = (const float*)d_in[10];
    float* out = (float*)d_out;

    const int gemm_smem = 4 * GTILE * 4;                                  // 73728
    const int attn_smem = (128 * QS_LD + 2 * KTILE + 2 * VTILE) * 4;      // 106496

    cudaFuncSetAttribute(gemm_tf32<0>, cudaFuncAttributeMaxDynamicSharedMemorySize, gemm_smem);
    cudaFuncSetAttribute(gemm_tf32<1>, cudaFuncAttributeMaxDynamicSharedMemorySize, gemm_smem);
    cudaFuncSetAttribute(gemm_tf32<2>, cudaFuncAttributeMaxDynamicSharedMemorySize, gemm_smem);
    cudaFuncSetAttribute(gemm_tf32<3>, cudaFuncAttributeMaxDynamicSharedMemorySize, gemm_smem);
    cudaFuncSetAttribute(attn_tf32, cudaFuncAttributeMaxDynamicSharedMemorySize, attn_smem);

    prep_round<<<dim3(1024, 7), 256>>>(query, key, value,
                                       (const float*)d_in[3], (const float*)d_in[5],
                                       (const float*)d_in[7], (const float*)d_in[9]);

    dim3 ggrid(DM_ / 128, MTOT / 128);   // (8, 32)
    gemm_tf32<1><<<ggrid, 256, gemm_smem>>>(bq, nullptr);
    gemm_tf32<2><<<ggrid, 256, gemm_smem>>>(bk, nullptr);
    gemm_tf32<3><<<ggrid, 256, gemm_smem>>>(bv, nullptr);

    attn_tf32<<<dim3(S_ / 128, B_ * H_), 256, attn_smem>>>();

    gemm_tf32<0><<<ggrid, 256, gemm_smem>>>(bo, out);
}

// round 8
// speedup vs baseline: 4.1960x; 1.0734x over previous
#include <cuda_runtime.h>
#include <cstdint>
#include <math.h>

#define B_ 2
#define S_ 2048
#define DM_ 1024
#define H_ 16
#define HD_ 64
#define MTOT (B_ * S_)      // 4096

#define fu __float_as_uint
#define uf __uint_as_float

// Scratch (allocation-free: __device__ globals; referenced ONLY in device code)
__device__ float g_Q[(size_t)B_ * H_ * S_ * HD_];   // head-major [B,H,S,HD], tf32-rounded
__device__ float g_K[(size_t)B_ * H_ * S_ * HD_];
__device__ float g_V[(size_t)B_ * H_ * S_ * HD_];
__device__ float g_O[(size_t)B_ * S_ * DM_];        // row-major [B*S,DM], tf32-rounded
__device__ float g_Xq[(size_t)MTOT * DM_];          // tf32-rounded inputs
__device__ float g_Xk[(size_t)MTOT * DM_];
__device__ float g_Xv[(size_t)MTOT * DM_];
__device__ float g_Wq[(size_t)DM_ * DM_];           // tf32-rounded weights
__device__ float g_Wk[(size_t)DM_ * DM_];
__device__ float g_Wv[(size_t)DM_ * DM_];
__device__ float g_Wo[(size_t)DM_ * DM_];

__device__ __forceinline__ uint32_t f2tf(float f) {
    uint32_t r;
    asm("cvt.rna.tf32.f32 %0, %1;" : "=r"(r) : "f"(f));
    return r;
}

__device__ __forceinline__ void mma_tf32(float c[4],
                                         uint32_t a0, uint32_t a1, uint32_t a2, uint32_t a3,
                                         uint32_t b0, uint32_t b1) {
    asm volatile(
        "mma.sync.aligned.m16n8k8.row.col.f32.tf32.tf32.f32 "
        "{%0,%1,%2,%3}, {%4,%5,%6,%7}, {%8,%9}, {%0,%1,%2,%3};\n"
        : "+f"(c[0]), "+f"(c[1]), "+f"(c[2]), "+f"(c[3])
        : "r"(a0), "r"(a1), "r"(a2), "r"(a3), "r"(b0), "r"(b1));
}

// ldmatrix x4: four 8x(16B) tiles; lane group i supplies rows of matrix i.
__device__ __forceinline__ void ldsm4(uint32_t r[4], uint32_t addr) {
    asm volatile("ldmatrix.sync.aligned.m8n8.x4.shared.b16 {%0,%1,%2,%3}, [%4];"
                 : "=r"(r[0]), "=r"(r[1]), "=r"(r[2]), "=r"(r[3]) : "r"(addr));
}

__device__ __forceinline__ void cpa16(uint32_t dst, const void* src) {
    asm volatile("cp.async.cg.shared.global [%0], [%1], 16;" :: "r"(dst), "l"(src));
}
#define CP_COMMIT() asm volatile("cp.async.commit_group;")
#define CP_WAIT1()  asm volatile("cp.async.wait_group 1;")

// ---------------------------------------------------------------------------
// Prep: round inputs and weights to tf32 (RNA) once (elementwise, exact).
// ---------------------------------------------------------------------------
__global__ void prep_round(const float* __restrict__ q, const float* __restrict__ k,
                           const float* __restrict__ v, const float* __restrict__ wq,
                           const float* __restrict__ wk, const float* __restrict__ wv,
                           const float* __restrict__ wo)
{
    const float* src; float* dst; int n;
    switch (blockIdx.y) {
        case 0: src = q;  dst = g_Xq; n = MTOT * DM_; break;
        case 1: src = k;  dst = g_Xk; n = MTOT * DM_; break;
        case 2: src = v;  dst = g_Xv; n = MTOT * DM_; break;
        case 3: src = wq; dst = g_Wq; n = DM_ * DM_;  break;
        case 4: src = wk; dst = g_Wk; n = DM_ * DM_;  break;
        case 5: src = wv; dst = g_Wv; n = DM_ * DM_;  break;
        default: src = wo; dst = g_Wo; n = DM_ * DM_; break;
    }
    const int n4 = n >> 2;
    for (int i = blockIdx.x * blockDim.x + threadIdx.x; i < n4;
         i += gridDim.x * blockDim.x) {
        float4 x = ((const float4*)src)[i];
        x.x = uf(f2tf(x.x)); x.y = uf(f2tf(x.y));
        x.z = uf(f2tf(x.z)); x.w = uf(f2tf(x.w));
        ((float4*)dst)[i] = x;
    }
}

// ---------------------------------------------------------------------------
// tf32 GEMM body (cp.async double-buffered, ldmatrix fragment loads).
// MODE 0: X=g_O, W=g_Wo -> final output Y (fp32).
// MODE 1: merged QKV — blockIdx.z selects {Xq,Wq,bq->g_Q}, {Xk,..}, {Xv,..}.
// Block 128x128, BK=32, 256 threads (8 warps 2x4), warp tile 64x32, occ 2.
// ---------------------------------------------------------------------------
#define GTILE (128 * 36)

template <int MODE>
__global__ __launch_bounds__(256, 2)
void gemm_tf32(const float* __restrict__ bias0, const float* __restrict__ bias1,
               const float* __restrict__ bias2, float* __restrict__ Y)
{
    const int z = (MODE == 0) ? 0 : blockIdx.z;
    const float* X = (MODE == 0) ? g_O
                   : (z == 0) ? g_Xq : (z == 1) ? g_Xk : g_Xv;
    const float* W = (MODE == 0) ? g_Wo
                   : (z == 0) ? g_Wq : (z == 1) ? g_Wk : g_Wv;
    const float* bias = (MODE == 0) ? bias0
                      : (z == 0) ? bias0 : (z == 1) ? bias1 : bias2;

    extern __shared__ float smg[];
    float* As = smg;              // [2][128][36]
    float* Bs = smg + 2 * GTILE;  // [2][128][36]
    const uint32_t sA = (uint32_t)__cvta_generic_to_shared(As);
    const uint32_t sB = (uint32_t)__cvta_generic_to_shared(Bs);

    const int tid  = threadIdx.x;
    const int warp = tid >> 5, lane = tid & 31;
    const int g  = lane >> 2, tg = lane & 3;
    const int wm = warp >> 2, wn = warp & 3;
    const int bm = blockIdx.y * 128, bn = blockIdx.x * 128;

    float acc[4][4][4];
#pragma unroll
    for (int i = 0; i < 4; i++)
#pragma unroll
        for (int j = 0; j < 4; j++)
#pragma unroll
            for (int k = 0; k < 4; k++) acc[i][j][k] = 0.0f;

    const int lrow = tid >> 3;          // 0..31 -> row base
    const int lc4  = (tid & 7) << 2;    // 0..28

    // ldmatrix per-thread base offsets (elements)
    const int a_base = (wm * 64 + (lane & 15)) * 36 + ((lane >> 4) << 2);
    const int b_base = (wn * 32 + ((lane >> 4) << 3) + (lane & 7)) * 36
                     + (((lane >> 3) & 1) << 2);

    // prefetch tile 0
#pragma unroll
    for (int i = 0; i < 4; i++) {
        const int row = lrow + 32 * i;
        const uint32_t off = (uint32_t)(row * 36 + lc4) << 2;
        cpa16(sA + off, X + (size_t)(bm + row) * DM_ + lc4);
        cpa16(sB + off, W + (size_t)(bn + row) * DM_ + lc4);
    }
    CP_COMMIT();

    for (int t = 0; t < 32; t++) {
        if (t + 1 < 32) {
            const int k0 = (t + 1) * 32;
            const uint32_t bufo = (uint32_t)(((t + 1) & 1) * GTILE) << 2;
#pragma unroll
            for (int i = 0; i < 4; i++) {
                const int row = lrow + 32 * i;
                const uint32_t off = bufo + ((uint32_t)(row * 36 + lc4) << 2);
                cpa16(sA + off, X + (size_t)(bm + row) * DM_ + k0 + lc4);
                cpa16(sB + off, W + (size_t)(bn + row) * DM_ + k0 + lc4);
            }
        }
        CP_COMMIT();
        CP_WAIT1();
        __syncthreads();

        const uint32_t bufb = (uint32_t)((t & 1) * GTILE) << 2;
        const uint32_t sAb = sA + bufb;
        const uint32_t sBb = sB + bufb;
#pragma unroll
        for (int ks = 0; ks < 4; ks++) {
            const int kk = ks * 8;
            uint32_t af[4][4], bfp[2][4];
#pragma unroll
            for (int mi = 0; mi < 4; mi++)
                ldsm4(af[mi], sAb + ((uint32_t)(a_base + mi * 16 * 36 + kk) << 2));
#pragma unroll
            for (int p = 0; p < 2; p++)
                ldsm4(bfp[p], sBb + ((uint32_t)(b_base + p * 16 * 36 + kk) << 2));
#pragma unroll
            for (int mi = 0; mi < 4; mi++)
#pragma unroll
                for (int p = 0; p < 2; p++) {
                    mma_tf32(acc[mi][2 * p],     af[mi][0], af[mi][1], af[mi][2], af[mi][3],
                             bfp[p][0], bfp[p][1]);
                    mma_tf32(acc[mi][2 * p + 1], af[mi][0], af[mi][1], af[mi][2], af[mi][3],
                             bfp[p][2], bfp[p][3]);
                }
        }
        __syncthreads();
    }

    // epilogue
#pragma unroll
    for (int mi = 0; mi < 4; mi++) {
#pragma unroll
        for (int ni = 0; ni < 4; ni++) {
            const int m = bm + wm * 64 + mi * 16 + g;
            const int n = bn + wn * 32 + ni * 8 + 2 * tg;
            const float b0 = bias[n], b1 = bias[n + 1];
            float v00 = acc[mi][ni][0] + b0;
            float v01 = acc[mi][ni][1] + b1;
            float v10 = acc[mi][ni][2] + b0;
            float v11 = acc[mi][ni][3] + b1;
            if (MODE == 0) {
                *(float2*)(Y + (size_t)m * DM_ + n)       = make_float2(v00, v01);
                *(float2*)(Y + (size_t)(m + 8) * DM_ + n) = make_float2(v10, v11);
            } else {
                v00 = uf(f2tf(v00)); v01 = uf(f2tf(v01));
                v10 = uf(f2tf(v10)); v11 = uf(f2tf(v11));
                float* dst = (z == 0) ? g_Q : (z == 1) ? g_K : g_V;
                const int h_ = n >> 6, d_ = n & (HD_ - 1);
                {
                    const int b_ = m >> 11, s_ = m & (S_ - 1);
                    *(float2*)(dst + (((size_t)b_ * H_ + h_) * S_ + s_) * HD_ + d_) =
                        make_float2(v00, v01);
                }
                {
                    const int m2 = m + 8;
                    const int b_ = m2 >> 11, s_ = m2 & (S_ - 1);
                    *(float2*)(dst + (((size_t)b_ * H_ + h_) * S_ + s_) * HD_ + d_) =
                        make_float2(v10, v11);
                }
            }
        }
    }
}

// ---------------------------------------------------------------------------
// Flash attention, softmax-one, tf32 mma, cp.async double-buffered K/V, occ 2,
// ldmatrix for K-frags and P-frags. Bc=64 as two 32-col chunks.
// O computed transposed (O^T = V^T @ P^T).
// ---------------------------------------------------------------------------
#define QS_LD 68
#define KS_LD 68
#define VS_LD 72
#define KTILE (64 * KS_LD)
#define VTILE (64 * VS_LD)

__global__ __launch_bounds__(256, 2)
void attn_tf32()
{
    extern __shared__ float sm[];
    float* Qs = sm;                       // 128*68 (reused as Ps)
    float* Ks = sm + 128 * QS_LD;         // [2][64][68]
    float* Vs = Ks + 2 * KTILE;           // [2][64][72]
    const uint32_t sQ = (uint32_t)__cvta_generic_to_shared(Qs);
    const uint32_t sK = (uint32_t)__cvta_generic_to_shared(Ks);
    const uint32_t sV = (uint32_t)__cvta_generic_to_shared(Vs);

    const int tid  = threadIdx.x;
    const int warp = tid >> 5, lane = tid & 31;
    const int g = lane >> 2, tg = lane & 3;
    const int bh = blockIdx.y;
    const int q0blk = blockIdx.x * 128;
    const int b = bh >> 4, h = bh & (H_ - 1);

    const float* Qg = g_Q + ((size_t)bh * S_ + q0blk) * HD_;
    const float* Kg = g_K + (size_t)bh * S_ * HD_;
    const float* Vg = g_V + (size_t)bh * S_ * HD_;

    const int lrow16 = tid >> 4;          // 0..15
    const int lc4    = (tid & 15) << 2;   // 0..60

    // ldmatrix per-thread base offsets (elements)
    const int k_base = (((lane >> 4) << 3) + (lane & 7)) * KS_LD
                     + (((lane >> 3) & 1) << 2);
    const int p_base = (warp * 16 + (lane & 15)) * QS_LD + ((lane >> 4) << 2);

    // prefetch K/V tile 0
#pragma unroll
    for (int i = 0; i < 4; i++) {
        const int row = lrow16 + 16 * i;
        cpa16(sK + ((uint32_t)(row * KS_LD + lc4) << 2), Kg + (size_t)row * HD_ + lc4);
        cpa16(sV + ((uint32_t)(row * VS_LD + lc4) << 2), Vg + (size_t)row * HD_ + lc4);
    }
    CP_COMMIT();

    // stage Q tile, extract fragments (0.125 scale exact in tf32)
#pragma unroll
    for (int i = 0; i < 8; i++) {
        const int f = tid + 256 * i;
        const int row = f >> 4, d4 = (f & 15) << 2;
        *(float4*)&Qs[row * QS_LD + d4] = *(const float4*)(Qg + (size_t)row * HD_ + d4);
    }
    __syncthreads();

    uint32_t qf[8][4];
    const int qrow = warp * 16 + g;
#pragma unroll
    for (int ks = 0; ks < 8; ks++) {
        const int d = ks * 8 + tg;
        qf[ks][0] = fu(0.125f * Qs[qrow * QS_LD + d]);
        qf[ks][1] = fu(0.125f * Qs[(qrow + 8) * QS_LD + d]);
        qf[ks][2] = fu(0.125f * Qs[qrow * QS_LD + d + 4]);
        qf[ks][3] = fu(0.125f * Qs[(qrow + 8) * QS_LD + d + 4]);
    }
    __syncthreads();   // Qs now reusable as Ps

    float oacc[4][2][4];
#pragma unroll
    for (int i = 0; i < 4; i++)
#pragma unroll
        for (int j = 0; j < 2; j++)
#pragma unroll
            for (int k = 0; k < 4; k++) oacc[i][j][k] = 0.0f;

    float m0 = 0.0f, m1 = 0.0f;   // virtual zero logit
    float l0 = 1.0f, l1 = 1.0f;

    for (int t = 0; t < 32; t++) {
        if (t + 1 < 32) {
            const size_t gofs = (size_t)(t + 1) * 64;
            const uint32_t bK = (uint32_t)(((t + 1) & 1) * KTILE) << 2;
            const uint32_t bV = (uint32_t)(((t + 1) & 1) * VTILE) << 2;
#pragma unroll
            for (int i = 0; i < 4; i++) {
                const int row = lrow16 + 16 * i;
                cpa16(sK + bK + ((uint32_t)(row * KS_LD + lc4) << 2),
                      Kg + (gofs + row) * HD_ + lc4);
                cpa16(sV + bV + ((uint32_t)(row * VS_LD + lc4) << 2),
                      Vg + (gofs + row) * HD_ + lc4);
            }
        }
        CP_COMMIT();
        CP_WAIT1();
        __syncthreads();

        const uint32_t sKb = sK + (((uint32_t)(t & 1) * KTILE) << 2);
        const float* Vsb = Vs + (t & 1) * VTILE;

#pragma unroll
        for (int c = 0; c < 2; c++) {
            const int colbase = c * 32;
            float s[4][4];
#pragma unroll
            for (int nt = 0; nt < 4; nt++)
                s[nt][0] = s[nt][1] = s[nt][2] = s[nt][3] = 0.0f;

            // S chunk = Q @ K^T (K-frags via ldmatrix)
#pragma unroll
            for (int ks = 0; ks < 8; ks++) {
#pragma unroll
                for (int p = 0; p < 2; p++) {
                    uint32_t kf[4];
                    ldsm4(kf, sKb + ((uint32_t)(k_base + (colbase + p * 16) * KS_LD
                                                + ks * 8) << 2));
                    mma_tf32(s[2 * p],     qf[ks][0], qf[ks][1], qf[ks][2], qf[ks][3],
                             kf[0], kf[1]);
                    mma_tf32(s[2 * p + 1], qf[ks][0], qf[ks][1], qf[ks][2], qf[ks][3],
                             kf[2], kf[3]);
                }
            }

            // online softmax-one update (chunk composes with running m/l)
            float rm0 = m0, rm1 = m1;
#pragma unroll
            for (int nt = 0; nt < 4; nt++) {
                rm0 = fmaxf(rm0, fmaxf(s[nt][0], s[nt][1]));
                rm1 = fmaxf(rm1, fmaxf(s[nt][2], s[nt][3]));
            }
            rm0 = fmaxf(rm0, __shfl_xor_sync(0xffffffffu, rm0, 1));
            rm0 = fmaxf(rm0, __shfl_xor_sync(0xffffffffu, rm0, 2));
            rm1 = fmaxf(rm1, __shfl_xor_sync(0xffffffffu, rm1, 1));
            rm1 = fmaxf(rm1, __shfl_xor_sync(0xffffffffu, rm1, 2));

            const float corr0 = __expf(m0 - rm0);
            const float corr1 = __expf(m1 - rm1);

            float ls0 = 0.0f, ls1 = 0.0f;
#pragma unroll
            for (int nt = 0; nt < 4; nt++) {
                const float p00 = __expf(s[nt][0] - rm0);
                const float p01 = __expf(s[nt][1] - rm0);
                const float p10 = __expf(s[nt][2] - rm1);
                const float p11 = __expf(s[nt][3] - rm1);
                ls0 += p00 + p01;
                ls1 += p10 + p11;
                const int col = colbase + nt * 8 + 2 * tg;
                Qs[qrow * QS_LD + col]           = uf(f2tf(p00));
                Qs[qrow * QS_LD + col + 1]       = uf(f2tf(p01));
                Qs[(qrow + 8) * QS_LD + col]     = uf(f2tf(p10));
                Qs[(qrow + 8) * QS_LD + col + 1] = uf(f2tf(p11));
            }
            ls0 += __shfl_xor_sync(0xffffffffu, ls0, 1);
            ls0 += __shfl_xor_sync(0xffffffffu, ls0, 2);
            ls1 += __shfl_xor_sync(0xffffffffu, ls1, 1);
            ls1 += __shfl_xor_sync(0xffffffffu, ls1, 2);
            l0 = l0 * corr0 + ls0; m0 = rm0;
            l1 = l1 * corr1 + ls1; m1 = rm1;
            __syncwarp();

            // rescale O^T accumulators (corr per q-column via shuffle)
#pragma unroll
            for (int nt = 0; nt < 2; nt++) {
                const int ql0 = 2 * tg, ql1 = 2 * tg + 1;
                float c0a = __shfl_sync(0xffffffffu, corr0, ql0 * 4);
                float c0b = __shfl_sync(0xffffffffu, corr1, ql0 * 4);
                float c1a = __shfl_sync(0xffffffffu, corr0, ql1 * 4);
                float c1b = __shfl_sync(0xffffffffu, corr1, ql1 * 4);
                const float cq0 = (nt == 0) ? c0a : c0b;
                const float cq1 = (nt == 0) ? c1a : c1b;
#pragma unroll
                for (int dt = 0; dt < 4; dt++) {
                    oacc[dt][nt][0] *= cq0;
                    oacc[dt][nt][1] *= cq1;
                    oacc[dt][nt][2] *= cq0;
                    oacc[dt][nt][3] *= cq1;
                }
            }

            // O^T += V^T @ P^T (P-frags via ldmatrix; V A-frags scalar)
#pragma unroll
            for (int ks2 = 0; ks2 < 4; ks2++) {
                const int kk = colbase + ks2 * 8;
                uint32_t pr[4];
                ldsm4(pr, sQ + ((uint32_t)(p_base + kk) << 2));
                // pr: [0]=pb[0][0], [1]=pb[1][0], [2]=pb[0][1], [3]=pb[1][1]
#pragma unroll
                for (int dt = 0; dt < 4; dt++) {
                    const uint32_t a0 = fu(Vsb[(kk + tg) * VS_LD + dt * 16 + g]);
                    const uint32_t a1 = fu(Vsb[(kk + tg) * VS_LD + dt * 16 + g + 8]);
                    const uint32_t a2 = fu(Vsb[(kk + tg + 4) * VS_LD + dt * 16 + g]);
                    const uint32_t a3 = fu(Vsb[(kk + tg + 4) * VS_LD + dt * 16 + g + 8]);
                    mma_tf32(oacc[dt][0], a0, a1, a2, a3, pr[0], pr[2]);
                    mma_tf32(oacc[dt][1], a0, a1, a2, a3, pr[1], pr[3]);
                }
            }
        }
        __syncthreads();
    }

    // finalize: divide by l (per q-row), tf32-round, store O^T frags to g_O
    const float inv0 = 1.0f / l0;
    const float inv1 = 1.0f / l1;
    float ivq[2][2];
#pragma unroll
    for (int nt = 0; nt < 2; nt++) {
        const int ql0 = 2 * tg, ql1 = 2 * tg + 1;
        float a0 = __shfl_sync(0xffffffffu, inv0, ql0 * 4);
        float b0 = __shfl_sync(0xffffffffu, inv1, ql0 * 4);
        float a1 = __shfl_sync(0xffffffffu, inv0, ql1 * 4);
        float b1 = __shfl_sync(0xffffffffu, inv1, ql1 * 4);
        ivq[nt][0] = (nt == 0) ? a0 : b0;
        ivq[nt][1] = (nt == 0) ? a1 : b1;
    }

    const size_t obase = ((size_t)(b * S_ + q0blk + warp * 16)) * DM_ + h * HD_;
#pragma unroll
    for (int dt = 0; dt < 4; dt++) {
#pragma unroll
        for (int nt = 0; nt < 2; nt++) {
            const int d  = dt * 16 + g;
            const int ql = nt * 8 + 2 * tg;
            g_O[obase + (size_t)ql * DM_ + d]           = uf(f2tf(oacc[dt][nt][0] * ivq[nt][0]));
            g_O[obase + (size_t)(ql + 1) * DM_ + d]     = uf(f2tf(oacc[dt][nt][1] * ivq[nt][1]));
            g_O[obase + (size_t)ql * DM_ + d + 8]       = uf(f2tf(oacc[dt][nt][2] * ivq[nt][0]));
            g_O[obase + (size_t)(ql + 1) * DM_ + d + 8] = uf(f2tf(oacc[dt][nt][3] * ivq[nt][1]));
        }
    }
}

// ---------------------------------------------------------------------------
// Launch (only harness pointers cross the host/device boundary)
// ---------------------------------------------------------------------------
extern "C" void kernel_launch(void* const* d_in, const int* in_sizes, int n_in,
                              void* d_out, int out_size)
{
    const float* query = (const float*)d_in[0];
    const float* key   = (const float*)d_in[1];
    const float* value = (const float*)d_in[2];
    const float* bq = (const float*)d_in[4];
    const float* bk = (const float*)d_in[6];
    const float* bv = (const float*)d_in[8];
    const float* bo = (const float*)d_in[10];
    float* out = (float*)d_out;

    const int gemm_smem = 4 * GTILE * 4;                                  // 73728
    const int attn_smem = (128 * QS_LD + 2 * KTILE + 2 * VTILE) * 4;      // 106496

    cudaFuncSetAttribute(gemm_tf32<0>, cudaFuncAttributeMaxDynamicSharedMemorySize, gemm_smem);
    cudaFuncSetAttribute(gemm_tf32<1>, cudaFuncAttributeMaxDynamicSharedMemorySize, gemm_smem);
    cudaFuncSetAttribute(attn_tf32, cudaFuncAttributeMaxDynamicSharedMemorySize, attn_smem);

    prep_round<<<dim3(1024, 7), 256>>>(query, key, value,
                                       (const float*)d_in[3], (const float*)d_in[5],
                                       (const float*)d_in[7], (const float*)d_in[9]);

    // merged QKV projections: grid.z selects q/k/v
    gemm_tf32<1><<<dim3(DM_ / 128, MTOT / 128, 3), 256, gemm_smem>>>(bq, bk, bv, nullptr);

    attn_tf32<<<dim3(S_ / 128, B_ * H_), 256, attn_smem>>>();

    gemm_tf32<0><<<dim3(DM_ / 128, MTOT / 128, 1), 256, gemm_smem>>>(bo, nullptr, nullptr, out);
}

// round 9
// speedup vs baseline: 4.2812x; 1.0203x over previous
#include <cuda_runtime.h>
#include <cstdint>
#include <math.h>

#define B_ 2
#define S_ 2048
#define DM_ 1024
#define H_ 16
#define HD_ 64
#define MTOT (B_ * S_)      // 4096

#define fu __float_as_uint
#define uf __uint_as_float

// Scratch (allocation-free: __device__ globals; referenced ONLY in device code)
__device__ float g_Q[(size_t)B_ * H_ * S_ * HD_];   // [B,H,S,HD], tf32-rounded
__device__ float g_K[(size_t)B_ * H_ * S_ * HD_];   // [B,H,S,HD], tf32-rounded
__device__ float g_Vt[(size_t)B_ * H_ * HD_ * S_];  // [B,H,HD,S] TRANSPOSED, tf32-rounded
__device__ float g_O[(size_t)B_ * S_ * DM_];        // [B*S,DM], tf32-rounded
__device__ float g_Xq[(size_t)MTOT * DM_];          // tf32-rounded inputs
__device__ float g_Xk[(size_t)MTOT * DM_];
__device__ float g_Xv[(size_t)MTOT * DM_];
__device__ float g_Wq[(size_t)DM_ * DM_];           // tf32-rounded weights
__device__ float g_Wk[(size_t)DM_ * DM_];
__device__ float g_Wv[(size_t)DM_ * DM_];
__device__ float g_Wo[(size_t)DM_ * DM_];

__device__ __forceinline__ uint32_t f2tf(float f) {
    uint32_t r;
    asm("cvt.rna.tf32.f32 %0, %1;" : "=r"(r) : "f"(f));
    return r;
}

__device__ __forceinline__ void mma_tf32(float c[4],
                                         uint32_t a0, uint32_t a1, uint32_t a2, uint32_t a3,
                                         uint32_t b0, uint32_t b1) {
    asm volatile(
        "mma.sync.aligned.m16n8k8.row.col.f32.tf32.tf32.f32 "
        "{%0,%1,%2,%3}, {%4,%5,%6,%7}, {%8,%9}, {%0,%1,%2,%3};\n"
        : "+f"(c[0]), "+f"(c[1]), "+f"(c[2]), "+f"(c[3])
        : "r"(a0), "r"(a1), "r"(a2), "r"(a3), "r"(b0), "r"(b1));
}

__device__ __forceinline__ void ldsm4(uint32_t r[4], uint32_t addr) {
    asm volatile("ldmatrix.sync.aligned.m8n8.x4.shared.b16 {%0,%1,%2,%3}, [%4];"
                 : "=r"(r[0]), "=r"(r[1]), "=r"(r[2]), "=r"(r[3]) : "r"(addr));
}

__device__ __forceinline__ void cpa16(uint32_t dst, const void* src) {
    asm volatile("cp.async.cg.shared.global [%0], [%1], 16;" :: "r"(dst), "l"(src));
}
#define CP_COMMIT() asm volatile("cp.async.commit_group;")
#define CP_WAIT0()  asm volatile("cp.async.wait_group 0;")

// ---------------------------------------------------------------------------
// Prep: round inputs and weights to tf32 (RNA) once (elementwise, exact).
// ---------------------------------------------------------------------------
__global__ void prep_round(const float* __restrict__ q, const float* __restrict__ k,
                           const float* __restrict__ v, const float* __restrict__ wq,
                           const float* __restrict__ wk, const float* __restrict__ wv,
                           const float* __restrict__ wo)
{
    const float* src; float* dst; int n;
    switch (blockIdx.y) {
        case 0: src = q;  dst = g_Xq; n = MTOT * DM_; break;
        case 1: src = k;  dst = g_Xk; n = MTOT * DM_; break;
        case 2: src = v;  dst = g_Xv; n = MTOT * DM_; break;
        case 3: src = wq; dst = g_Wq; n = DM_ * DM_;  break;
        case 4: src = wk; dst = g_Wk; n = DM_ * DM_;  break;
        case 5: src = wv; dst = g_Wv; n = DM_ * DM_;  break;
        default: src = wo; dst = g_Wo; n = DM_ * DM_; break;
    }
    const int n4 = n >> 2;
    for (int i = blockIdx.x * blockDim.x + threadIdx.x; i < n4;
         i += gridDim.x * blockDim.x) {
        float4 x = ((const float4*)src)[i];
        x.x = uf(f2tf(x.x)); x.y = uf(f2tf(x.y));
        x.z = uf(f2tf(x.z)); x.w = uf(f2tf(x.w));
        ((float4*)dst)[i] = x;
    }
}

// ---------------------------------------------------------------------------
// tf32 GEMM: cp.async double-buffered, SINGLE sync per k-tile (race-free
// order: wait0 -> sync -> prefetch(t+1) -> compute(t)).
// MODE 0: X=g_O, W=g_Wo -> final output Y. MODE 1: merged QKV via blockIdx.z;
// z==2 (V) writes TRANSPOSED into g_Vt[b,h,d,s].
// ---------------------------------------------------------------------------
#define GTILE (128 * 36)

template <int MODE>
__global__ __launch_bounds__(256, 2)
void gemm_tf32(const float* __restrict__ bias0, const float* __restrict__ bias1,
               const float* __restrict__ bias2, float* __restrict__ Y)
{
    const int z = (MODE == 0) ? 0 : blockIdx.z;
    const float* X = (MODE == 0) ? g_O
                   : (z == 0) ? g_Xq : (z == 1) ? g_Xk : g_Xv;
    const float* W = (MODE == 0) ? g_Wo
                   : (z == 0) ? g_Wq : (z == 1) ? g_Wk : g_Wv;
    const float* bias = (MODE == 0) ? bias0
                      : (z == 0) ? bias0 : (z == 1) ? bias1 : bias2;

    extern __shared__ float smg[];
    float* As = smg;              // [2][128][36]
    float* Bs = smg + 2 * GTILE;  // [2][128][36]
    const uint32_t sA = (uint32_t)__cvta_generic_to_shared(As);
    const uint32_t sB = (uint32_t)__cvta_generic_to_shared(Bs);

    const int tid  = threadIdx.x;
    const int warp = tid >> 5, lane = tid & 31;
    const int g  = lane >> 2, tg = lane & 3;
    const int wm = warp >> 2, wn = warp & 3;
    const int bm = blockIdx.y * 128, bn = blockIdx.x * 128;

    float acc[4][4][4];
#pragma unroll
    for (int i = 0; i < 4; i++)
#pragma unroll
        for (int j = 0; j < 4; j++)
#pragma unroll
            for (int k = 0; k < 4; k++) acc[i][j][k] = 0.0f;

    const int lrow = tid >> 3;          // 0..31 -> row base
    const int lc4  = (tid & 7) << 2;    // 0..28

    const int a_base = (wm * 64 + (lane & 15)) * 36 + ((lane >> 4) << 2);
    const int b_base = (wn * 32 + ((lane >> 4) << 3) + (lane & 7)) * 36
                     + (((lane >> 3) & 1) << 2);

    // prefetch tile 0
#pragma unroll
    for (int i = 0; i < 4; i++) {
        const int row = lrow + 32 * i;
        const uint32_t off = (uint32_t)(row * 36 + lc4) << 2;
        cpa16(sA + off, X + (size_t)(bm + row) * DM_ + lc4);
        cpa16(sB + off, W + (size_t)(bn + row) * DM_ + lc4);
    }
    CP_COMMIT();

    for (int t = 0; t < 32; t++) {
        CP_WAIT0();          // tile t arrived
        __syncthreads();     // everyone done computing t-1; tile t visible

        if (t + 1 < 32) {    // safe now: t-1 readers of buf[(t+1)&1] are done
            const int k0 = (t + 1) * 32;
            const uint32_t bufo = (uint32_t)(((t + 1) & 1) * GTILE) << 2;
#pragma unroll
            for (int i = 0; i < 4; i++) {
                const int row = lrow + 32 * i;
                const uint32_t off = bufo + ((uint32_t)(row * 36 + lc4) << 2);
                cpa16(sA + off, X + (size_t)(bm + row) * DM_ + k0 + lc4);
                cpa16(sB + off, W + (size_t)(bn + row) * DM_ + k0 + lc4);
            }
            CP_COMMIT();
        }

        const uint32_t bufb = (uint32_t)((t & 1) * GTILE) << 2;
        const uint32_t sAb = sA + bufb;
        const uint32_t sBb = sB + bufb;
#pragma unroll
        for (int ks = 0; ks < 4; ks++) {
            const int kk = ks * 8;
            uint32_t af[4][4], bfp[2][4];
#pragma unroll
            for (int mi = 0; mi < 4; mi++)
                ldsm4(af[mi], sAb + ((uint32_t)(a_base + mi * 16 * 36 + kk) << 2));
#pragma unroll
            for (int p = 0; p < 2; p++)
                ldsm4(bfp[p], sBb + ((uint32_t)(b_base + p * 16 * 36 + kk) << 2));
#pragma unroll
            for (int mi = 0; mi < 4; mi++)
#pragma unroll
                for (int p = 0; p < 2; p++) {
                    mma_tf32(acc[mi][2 * p],     af[mi][0], af[mi][1], af[mi][2], af[mi][3],
                             bfp[p][0], bfp[p][1]);
                    mma_tf32(acc[mi][2 * p + 1], af[mi][0], af[mi][1], af[mi][2], af[mi][3],
                             bfp[p][2], bfp[p][3]);
                }
        }
    }

    // epilogue
#pragma unroll
    for (int mi = 0; mi < 4; mi++) {
#pragma unroll
        for (int ni = 0; ni < 4; ni++) {
            const int m = bm + wm * 64 + mi * 16 + g;
            const int n = bn + wn * 32 + ni * 8 + 2 * tg;
            const float b0 = bias[n], b1 = bias[n + 1];
            float v00 = acc[mi][ni][0] + b0;
            float v01 = acc[mi][ni][1] + b1;
            float v10 = acc[mi][ni][2] + b0;
            float v11 = acc[mi][ni][3] + b1;
            if (MODE == 0) {
                *(float2*)(Y + (size_t)m * DM_ + n)       = make_float2(v00, v01);
                *(float2*)(Y + (size_t)(m + 8) * DM_ + n) = make_float2(v10, v11);
            } else {
                v00 = uf(f2tf(v00)); v01 = uf(f2tf(v01));
                v10 = uf(f2tf(v10)); v11 = uf(f2tf(v11));
                const int h_ = n >> 6, d_ = n & (HD_ - 1);
                if (z == 2) {
                    // V transposed: [B,H,HD,S]
                    {
                        const int b_ = m >> 11, s_ = m & (S_ - 1);
                        float* base = g_Vt + (((size_t)b_ * H_ + h_) * HD_ + d_) * S_ + s_;
                        base[0] = v00; base[S_] = v01;
                    }
                    {
                        const int m2 = m + 8;
                        const int b_ = m2 >> 11, s_ = m2 & (S_ - 1);
                        float* base = g_Vt + (((size_t)b_ * H_ + h_) * HD_ + d_) * S_ + s_;
                        base[0] = v10; base[S_] = v11;
                    }
                } else {
                    float* dst = (z == 0) ? g_Q : g_K;
                    {
                        const int b_ = m >> 11, s_ = m & (S_ - 1);
                        *(float2*)(dst + (((size_t)b_ * H_ + h_) * S_ + s_) * HD_ + d_) =
                            make_float2(v00, v01);
                    }
                    {
                        const int m2 = m + 8;
                        const int b_ = m2 >> 11, s_ = m2 & (S_ - 1);
                        *(float2*)(dst + (((size_t)b_ * H_ + h_) * S_ + s_) * HD_ + d_) =
                            make_float2(v10, v11);
                    }
                }
            }
        }
    }
}

// ---------------------------------------------------------------------------
// Flash attention, softmax-one, tf32 mma, cp.async double-buffered K/Vt,
// occ 2, ldmatrix for K-, P- AND V-fragments (V stored transposed).
// Single sync per tile (race-free order). O computed transposed.
// ---------------------------------------------------------------------------
#define QS_LD 68
#define KS_LD 68
#define VT_LD 68
#define KTILE (64 * KS_LD)
#define VTILE (64 * VT_LD)

__global__ __launch_bounds__(256, 2)
void attn_tf32()
{
    extern __shared__ float sm[];
    float* Qs  = sm;                      // 128*68 (reused as Ps)
    float* Ks  = sm + 128 * QS_LD;        // [2][64][68]
    float* Vts = Ks + 2 * KTILE;          // [2][64][68]  (rows = d, cols = kc)
    const uint32_t sQ = (uint32_t)__cvta_generic_to_shared(Qs);
    const uint32_t sK = (uint32_t)__cvta_generic_to_shared(Ks);
    const uint32_t sV = (uint32_t)__cvta_generic_to_shared(Vts);

    const int tid  = threadIdx.x;
    const int warp = tid >> 5, lane = tid & 31;
    const int g = lane >> 2, tg = lane & 3;
    const int bh = blockIdx.y;
    const int q0blk = blockIdx.x * 128;
    const int b = bh >> 4, h = bh & (H_ - 1);

    const float* Qg  = g_Q + ((size_t)bh * S_ + q0blk) * HD_;
    const float* Kg  = g_K + (size_t)bh * S_ * HD_;
    const float* Vtg = g_Vt + (size_t)bh * HD_ * S_;

    const int lrow16 = tid >> 4;          // 0..15
    const int lc4    = (tid & 15) << 2;   // 0..60

    // ldmatrix per-thread base offsets (elements)
    const int k_base  = (((lane >> 4) << 3) + (lane & 7)) * KS_LD
                      + (((lane >> 3) & 1) << 2);
    const int p_base  = (warp * 16 + (lane & 15)) * QS_LD + ((lane >> 4) << 2);
    const int vt_base = (lane & 15) * VT_LD + ((lane >> 4) << 2);

    // prefetch K/Vt tile 0  (Vt rows are head-dims, cols are kc positions)
#pragma unroll
    for (int i = 0; i < 4; i++) {
        const int row = lrow16 + 16 * i;
        cpa16(sK + ((uint32_t)(row * KS_LD + lc4) << 2), Kg + (size_t)row * HD_ + lc4);
        cpa16(sV + ((uint32_t)(row * VT_LD + lc4) << 2), Vtg + (size_t)row * S_ + lc4);
    }
    CP_COMMIT();

    // stage Q tile, extract fragments (0.125 scale exact in tf32)
#pragma unroll
    for (int i = 0; i < 8; i++) {
        const int f = tid + 256 * i;
        const int row = f >> 4, d4 = (f & 15) << 2;
        *(float4*)&Qs[row * QS_LD + d4] = *(const float4*)(Qg + (size_t)row * HD_ + d4);
    }
    __syncthreads();

    uint32_t qf[8][4];
    const int qrow = warp * 16 + g;
#pragma unroll
    for (int ks = 0; ks < 8; ks++) {
        const int d = ks * 8 + tg;
        qf[ks][0] = fu(0.125f * Qs[qrow * QS_LD + d]);
        qf[ks][1] = fu(0.125f * Qs[(qrow + 8) * QS_LD + d]);
        qf[ks][2] = fu(0.125f * Qs[qrow * QS_LD + d + 4]);
        qf[ks][3] = fu(0.125f * Qs[(qrow + 8) * QS_LD + d + 4]);
    }
    __syncthreads();   // Qs now reusable as Ps

    float oacc[4][2][4];
#pragma unroll
    for (int i = 0; i < 4; i++)
#pragma unroll
        for (int j = 0; j < 2; j++)
#pragma unroll
            for (int k = 0; k < 4; k++) oacc[i][j][k] = 0.0f;

    float m0 = 0.0f, m1 = 0.0f;   // virtual zero logit
    float l0 = 1.0f, l1 = 1.0f;

    for (int t = 0; t < 32; t++) {
        CP_WAIT0();          // tile t arrived
        __syncthreads();     // all warps done with tile t-1

        if (t + 1 < 32) {
            const size_t gofs = (size_t)(t + 1) * 64;
            const uint32_t bK = (uint32_t)(((t + 1) & 1) * KTILE) << 2;
            const uint32_t bV = (uint32_t)(((t + 1) & 1) * VTILE) << 2;
#pragma unroll
            for (int i = 0; i < 4; i++) {
                const int row = lrow16 + 16 * i;
                cpa16(sK + bK + ((uint32_t)(row * KS_LD + lc4) << 2),
                      Kg + (gofs + row) * HD_ + lc4);
                cpa16(sV + bV + ((uint32_t)(row * VT_LD + lc4) << 2),
                      Vtg + (size_t)row * S_ + gofs + lc4);
            }
            CP_COMMIT();
        }

        const uint32_t sKb = sK + (((uint32_t)(t & 1) * KTILE) << 2);
        const uint32_t sVb = sV + (((uint32_t)(t & 1) * VTILE) << 2);

#pragma unroll
        for (int c = 0; c < 2; c++) {
            const int colbase = c * 32;
            float s[4][4];
#pragma unroll
            for (int nt = 0; nt < 4; nt++)
                s[nt][0] = s[nt][1] = s[nt][2] = s[nt][3] = 0.0f;

            // S chunk = Q @ K^T (K-frags via ldmatrix)
#pragma unroll
            for (int ks = 0; ks < 8; ks++) {
#pragma unroll
                for (int p = 0; p < 2; p++) {
                    uint32_t kf[4];
                    ldsm4(kf, sKb + ((uint32_t)(k_base + (colbase + p * 16) * KS_LD
                                                + ks * 8) << 2));
                    mma_tf32(s[2 * p],     qf[ks][0], qf[ks][1], qf[ks][2], qf[ks][3],
                             kf[0], kf[1]);
                    mma_tf32(s[2 * p + 1], qf[ks][0], qf[ks][1], qf[ks][2], qf[ks][3],
                             kf[2], kf[3]);
                }
            }

            // online softmax-one update
            float rm0 = m0, rm1 = m1;
#pragma unroll
            for (int nt = 0; nt < 4; nt++) {
                rm0 = fmaxf(rm0, fmaxf(s[nt][0], s[nt][1]));
                rm1 = fmaxf(rm1, fmaxf(s[nt][2], s[nt][3]));
            }
            rm0 = fmaxf(rm0, __shfl_xor_sync(0xffffffffu, rm0, 1));
            rm0 = fmaxf(rm0, __shfl_xor_sync(0xffffffffu, rm0, 2));
            rm1 = fmaxf(rm1, __shfl_xor_sync(0xffffffffu, rm1, 1));
            rm1 = fmaxf(rm1, __shfl_xor_sync(0xffffffffu, rm1, 2));

            const float corr0 = __expf(m0 - rm0);
            const float corr1 = __expf(m1 - rm1);

            float ls0 = 0.0f, ls1 = 0.0f;
#pragma unroll
            for (int nt = 0; nt < 4; nt++) {
                const float p00 = __expf(s[nt][0] - rm0);
                const float p01 = __expf(s[nt][1] - rm0);
                const float p10 = __expf(s[nt][2] - rm1);
                const float p11 = __expf(s[nt][3] - rm1);
                ls0 += p00 + p01;
                ls1 += p10 + p11;
                const int col = colbase + nt * 8 + 2 * tg;
                Qs[qrow * QS_LD + col]           = uf(f2tf(p00));
                Qs[qrow * QS_LD + col + 1]       = uf(f2tf(p01));
                Qs[(qrow + 8) * QS_LD + col]     = uf(f2tf(p10));
                Qs[(qrow + 8) * QS_LD + col + 1] = uf(f2tf(p11));
            }
            ls0 += __shfl_xor_sync(0xffffffffu, ls0, 1);
            ls0 += __shfl_xor_sync(0xffffffffu, ls0, 2);
            ls1 += __shfl_xor_sync(0xffffffffu, ls1, 1);
            ls1 += __shfl_xor_sync(0xffffffffu, ls1, 2);
            l0 = l0 * corr0 + ls0; m0 = rm0;
            l1 = l1 * corr1 + ls1; m1 = rm1;
            __syncwarp();

            // rescale O^T accumulators (corr per q-column via shuffle)
#pragma unroll
            for (int nt = 0; nt < 2; nt++) {
                const int ql0 = 2 * tg, ql1 = 2 * tg + 1;
                float c0a = __shfl_sync(0xffffffffu, corr0, ql0 * 4);
                float c0b = __shfl_sync(0xffffffffu, corr1, ql0 * 4);
                float c1a = __shfl_sync(0xffffffffu, corr0, ql1 * 4);
                float c1b = __shfl_sync(0xffffffffu, corr1, ql1 * 4);
                const float cq0 = (nt == 0) ? c0a : c0b;
                const float cq1 = (nt == 0) ? c1a : c1b;
#pragma unroll
                for (int dt = 0; dt < 4; dt++) {
                    oacc[dt][nt][0] *= cq0;
                    oacc[dt][nt][1] *= cq1;
                    oacc[dt][nt][2] *= cq0;
                    oacc[dt][nt][3] *= cq1;
                }
            }

            // O^T += V^T @ P^T (both operands via ldmatrix now)
#pragma unroll
            for (int ks2 = 0; ks2 < 4; ks2++) {
                const int kk = colbase + ks2 * 8;
                uint32_t pr[4];
                ldsm4(pr, sQ + ((uint32_t)(p_base + kk) << 2));
#pragma unroll
                for (int dt = 0; dt < 4; dt++) {
                    uint32_t vf[4];
                    ldsm4(vf, sVb + ((uint32_t)(vt_base + dt * 16 * VT_LD + kk) << 2));
                    mma_tf32(oacc[dt][0], vf[0], vf[1], vf[2], vf[3], pr[0], pr[2]);
                    mma_tf32(oacc[dt][1], vf[0], vf[1], vf[2], vf[3], pr[1], pr[3]);
                }
            }
        }
    }

    // finalize: divide by l (per q-row), tf32-round, store O^T frags to g_O
    const float inv0 = 1.0f / l0;
    const float inv1 = 1.0f / l1;
    float ivq[2][2];
#pragma unroll
    for (int nt = 0; nt < 2; nt++) {
        const int ql0 = 2 * tg, ql1 = 2 * tg + 1;
        float a0 = __shfl_sync(0xffffffffu, inv0, ql0 * 4);
        float b0 = __shfl_sync(0xffffffffu, inv1, ql0 * 4);
        float a1 = __shfl_sync(0xffffffffu, inv0, ql1 * 4);
        float b1 = __shfl_sync(0xffffffffu, inv1, ql1 * 4);
        ivq[nt][0] = (nt == 0) ? a0 : b0;
        ivq[nt][1] = (nt == 0) ? a1 : b1;
    }

    const size_t obase = ((size_t)(b * S_ + q0blk + warp * 16)) * DM_ + h * HD_;
#pragma unroll
    for (int dt = 0; dt < 4; dt++) {
#pragma unroll
        for (int nt = 0; nt < 2; nt++) {
            const int d  = dt * 16 + g;
            const int ql = nt * 8 + 2 * tg;
            g_O[obase + (size_t)ql * DM_ + d]           = uf(f2tf(oacc[dt][nt][0] * ivq[nt][0]));
            g_O[obase + (size_t)(ql + 1) * DM_ + d]     = uf(f2tf(oacc[dt][nt][1] * ivq[nt][1]));
            g_O[obase + (size_t)ql * DM_ + d + 8]       = uf(f2tf(oacc[dt][nt][2] * ivq[nt][0]));
            g_O[obase + (size_t)(ql + 1) * DM_ + d + 8] = uf(f2tf(oacc[dt][nt][3] * ivq[nt][1]));
        }
    }
}

// ---------------------------------------------------------------------------
// Launch (only harness pointers cross the host/device boundary)
// ---------------------------------------------------------------------------
extern "C" void kernel_launch(void* const* d_in, const int* in_sizes, int n_in,
                              void* d_out, int out_size)
{
    const float* query = (const float*)d_in[0];
    const float* key   = (const float*)d_in[1];
    const float* value = (const float*)d_in[2];
    const float* bq = (const float*)d_in[4];
    const float* bk = (const float*)d_in[6];
    const float* bv = (const float*)d_in[8];
    const float* bo = (const float*)d_in[10];
    float* out = (float*)d_out;

    const int gemm_smem = 4 * GTILE * 4;                                  // 73728
    const int attn_smem = (128 * QS_LD + 2 * KTILE + 2 * VTILE) * 4;      // 104448

    cudaFuncSetAttribute(gemm_tf32<0>, cudaFuncAttributeMaxDynamicSharedMemorySize, gemm_smem);
    cudaFuncSetAttribute(gemm_tf32<1>, cudaFuncAttributeMaxDynamicSharedMemorySize, gemm_smem);
    cudaFuncSetAttribute(attn_tf32, cudaFuncAttributeMaxDynamicSharedMemorySize, attn_smem);

    prep_round<<<dim3(1024, 7), 256>>>(query, key, value,
                                       (const float*)d_in[3], (const float*)d_in[5],
                                       (const float*)d_in[7], (const float*)d_in[9]);

    // merged QKV projections: grid.z selects q/k/v
    gemm_tf32<1><<<dim3(DM_ / 128, MTOT / 128, 3), 256, gemm_smem>>>(bq, bk, bv, nullptr);

    attn_tf32<<<dim3(S_ / 128, B_ * H_), 256, attn_smem>>>();

    gemm_tf32<0><<<dim3(DM_ / 128, MTOT / 128, 1), 256, gemm_smem>>>(bo, nullptr, nullptr, out);
}

// round 11
// speedup vs baseline: 7.6457x; 1.7859x over previous
#include <cuda_runtime.h>
#include <cuda_fp16.h>
#include <cstdint>
#include <math.h>

#define B_ 2
#define S_ 2048
#define DM_ 1024
#define H_ 16
#define HD_ 64
#define MTOT (B_ * S_)      // 4096

#define fu __float_as_uint
#define uf __uint_as_float

// Scratch (allocation-free: __device__ globals; referenced ONLY in device code)
__device__ __half g_Q[(size_t)B_ * H_ * S_ * HD_];   // [B,H,S,HD], fp16, pre-scaled by 0.125
__device__ __half g_K[(size_t)B_ * H_ * S_ * HD_];   // [B,H,S,HD], fp16
__device__ __half g_Vt[(size_t)B_ * H_ * HD_ * S_];  // [B,H,HD,S] TRANSPOSED, fp16
__device__ __half g_O[(size_t)B_ * S_ * DM_];        // [B*S,DM], fp16
__device__ __half g_Xq[(size_t)MTOT * DM_];          // fp16 inputs
__device__ __half g_Xk[(size_t)MTOT * DM_];
__device__ __half g_Xv[(size_t)MTOT * DM_];
__device__ __half g_Wq[(size_t)DM_ * DM_];           // fp16 weights
__device__ __half g_Wk[(size_t)DM_ * DM_];
__device__ __half g_Wv[(size_t)DM_ * DM_];
__device__ __half g_Wo[(size_t)DM_ * DM_];

__device__ __forceinline__ uint32_t pk2(float a, float b) {
    __half2 h = __floats2half2_rn(a, b);
    return *reinterpret_cast<uint32_t*>(&h);
}

__device__ __forceinline__ void mma_f16(float c[4],
                                        uint32_t a0, uint32_t a1, uint32_t a2, uint32_t a3,
                                        uint32_t b0, uint32_t b1) {
    asm volatile(
        "mma.sync.aligned.m16n8k16.row.col.f32.f16.f16.f32 "
        "{%0,%1,%2,%3}, {%4,%5,%6,%7}, {%8,%9}, {%0,%1,%2,%3};\n"
        : "+f"(c[0]), "+f"(c[1]), "+f"(c[2]), "+f"(c[3])
        : "r"(a0), "r"(a1), "r"(a2), "r"(a3), "r"(b0), "r"(b1));
}

__device__ __forceinline__ void ldsm4(uint32_t r[4], uint32_t addr) {
    asm volatile("ldmatrix.sync.aligned.m8n8.x4.shared.b16 {%0,%1,%2,%3}, [%4];"
                 : "=r"(r[0]), "=r"(r[1]), "=r"(r[2]), "=r"(r[3]) : "r"(addr));
}

__device__ __forceinline__ void cpa16(uint32_t dst, const void* src) {
    asm volatile("cp.async.cg.shared.global [%0], [%1], 16;" :: "r"(dst), "l"(src));
}
#define CP_COMMIT() asm volatile("cp.async.commit_group;")
#define CP_WAIT0()  asm volatile("cp.async.wait_group 0;")

// ---------------------------------------------------------------------------
// Prep: convert inputs and weights to fp16 (rn) once (elementwise).
// ---------------------------------------------------------------------------
__global__ void prep_half(const float* __restrict__ q, const float* __restrict__ k,
                          const float* __restrict__ v, const float* __restrict__ wq,
                          const float* __restrict__ wk, const float* __restrict__ wv,
                          const float* __restrict__ wo)
{
    const float* src; __half* dst; int n;
    switch (blockIdx.y) {
        case 0: src = q;  dst = g_Xq; n = MTOT * DM_; break;
        case 1: src = k;  dst = g_Xk; n = MTOT * DM_; break;
        case 2: src = v;  dst = g_Xv; n = MTOT * DM_; break;
        case 3: src = wq; dst = g_Wq; n = DM_ * DM_;  break;
        case 4: src = wk; dst = g_Wk; n = DM_ * DM_;  break;
        case 5: src = wv; dst = g_Wv; n = DM_ * DM_;  break;
        default: src = wo; dst = g_Wo; n = DM_ * DM_; break;
    }
    const int n8 = n >> 3;
    for (int i = blockIdx.x * blockDim.x + threadIdx.x; i < n8;
         i += gridDim.x * blockDim.x) {
        float4 x0 = ((const float4*)src)[2 * i];
        float4 x1 = ((const float4*)src)[2 * i + 1];
        uint4 o;
        o.x = pk2(x0.x, x0.y); o.y = pk2(x0.z, x0.w);
        o.z = pk2(x1.x, x1.y); o.w = pk2(x1.z, x1.w);
        ((uint4*)dst)[i] = o;
    }
}

// ---------------------------------------------------------------------------
// fp16 GEMM: Y[m,n] = sum_k X[m,k]*W[n,k] + bias[n]
// cp.async double-buffered, single sync per k-tile, ldmatrix frags,
// m16n8k16 fp16 mma (fp32 accum). Tiles 128x128, BK=64 halves, ld=72 halves.
// MODE 0: X=g_O, W=g_Wo -> fp32 out. MODE 1: merged QKV via blockIdx.z
// (z==0 Q scaled by 0.125; z==2 V transposed into g_Vt). Scratch out fp16.
// ---------------------------------------------------------------------------
#define LDH 72
#define GTILEB (128 * LDH * 2)   // bytes per matrix buffer = 18432

template <int MODE>
__global__ __launch_bounds__(256, 2)
void gemm_f16(const float* __restrict__ bias0, const float* __restrict__ bias1,
              const float* __restrict__ bias2, float* __restrict__ Y)
{
    const int z = (MODE == 0) ? 0 : blockIdx.z;
    const __half* X = (MODE == 0) ? g_O : (z == 0) ? g_Xq : (z == 1) ? g_Xk : g_Xv;
    const __half* W = (MODE == 0) ? g_Wo : (z == 0) ? g_Wq : (z == 1) ? g_Wk : g_Wv;
    const float* bias = (MODE == 0) ? bias0 : (z == 0) ? bias0 : (z == 1) ? bias1 : bias2;

    extern __shared__ __half smh[];
    // layout: [A0][B0][A1][B1], each 128*72 halves
    const uint32_t sA = (uint32_t)__cvta_generic_to_shared(smh);
    const uint32_t sB = sA + GTILEB;

    const int tid  = threadIdx.x;
    const int warp = tid >> 5, lane = tid & 31;
    const int g  = lane >> 2, tg = lane & 3;
    const int wm = warp >> 2, wn = warp & 3;
    const int bm = blockIdx.y * 128, bn = blockIdx.x * 128;

    float acc[4][4][4];
#pragma unroll
    for (int i = 0; i < 4; i++)
#pragma unroll
        for (int j = 0; j < 4; j++)
#pragma unroll
            for (int k = 0; k < 4; k++) acc[i][j][k] = 0.0f;

    // fragment base offsets (halves)
    const int a_base = (wm * 64 + (lane & 15)) * LDH + ((lane >> 4) << 3);
    const int b_base = (wn * 32 + ((lane >> 4) << 3) + (lane & 7)) * LDH
                     + (((lane >> 3) & 1) << 3);

    // prefetch tile 0: per matrix 128 rows x 64 halves (8 x 16B chunks/row)
#pragma unroll
    for (int i = 0; i < 4; i++) {
        const int f = tid + 256 * i;
        const int row = f >> 3, ch = (f & 7) << 3;
        const uint32_t off = (uint32_t)(row * LDH + ch) << 1;
        cpa16(sA + off, X + (size_t)(bm + row) * DM_ + ch);
        cpa16(sB + off, W + (size_t)(bn + row) * DM_ + ch);
    }
    CP_COMMIT();

    for (int t = 0; t < 16; t++) {
        CP_WAIT0();          // tile t arrived
        __syncthreads();     // readers of t-1 done; tile t visible

        if (t + 1 < 16) {
            const int k0 = (t + 1) * 64;
            const uint32_t bufo = (uint32_t)(((t + 1) & 1) * 2 * GTILEB);
#pragma unroll
            for (int i = 0; i < 4; i++) {
                const int f = tid + 256 * i;
                const int row = f >> 3, ch = (f & 7) << 3;
                const uint32_t off = bufo + ((uint32_t)(row * LDH + ch) << 1);
                cpa16(sA + off, X + (size_t)(bm + row) * DM_ + k0 + ch);
                cpa16(sB + off, W + (size_t)(bn + row) * DM_ + k0 + ch);
            }
            CP_COMMIT();
        }

        const uint32_t bufb = (uint32_t)((t & 1) * 2 * GTILEB);
        const uint32_t sAb = sA + bufb;
        const uint32_t sBb = sB + bufb;
#pragma unroll
        for (int ks = 0; ks < 4; ks++) {
            const int kk = ks * 16;
            uint32_t af[4][4], bfp[2][4];
#pragma unroll
            for (int mi = 0; mi < 4; mi++)
                ldsm4(af[mi], sAb + ((uint32_t)(a_base + mi * 16 * LDH + kk) << 1));
#pragma unroll
            for (int p = 0; p < 2; p++)
                ldsm4(bfp[p], sBb + ((uint32_t)(b_base + p * 16 * LDH + kk) << 1));
#pragma unroll
            for (int mi = 0; mi < 4; mi++)
#pragma unroll
                for (int p = 0; p < 2; p++) {
                    mma_f16(acc[mi][2 * p],     af[mi][0], af[mi][1], af[mi][2], af[mi][3],
                            bfp[p][0], bfp[p][1]);
                    mma_f16(acc[mi][2 * p + 1], af[mi][0], af[mi][1], af[mi][2], af[mi][3],
                            bfp[p][2], bfp[p][3]);
                }
        }
    }

    // epilogue
#pragma unroll
    for (int mi = 0; mi < 4; mi++) {
#pragma unroll
        for (int ni = 0; ni < 4; ni++) {
            const int m = bm + wm * 64 + mi * 16 + g;
            const int n = bn + wn * 32 + ni * 8 + 2 * tg;
            const float b0 = bias[n], b1 = bias[n + 1];
            float v00 = acc[mi][ni][0] + b0;
            float v01 = acc[mi][ni][1] + b1;
            float v10 = acc[mi][ni][2] + b0;
            float v11 = acc[mi][ni][3] + b1;
            if (MODE == 0) {
                *(float2*)(Y + (size_t)m * DM_ + n)       = make_float2(v00, v01);
                *(float2*)(Y + (size_t)(m + 8) * DM_ + n) = make_float2(v10, v11);
            } else {
                if (z == 0) { v00 *= 0.125f; v01 *= 0.125f; v10 *= 0.125f; v11 *= 0.125f; }
                const int h_ = n >> 6, d_ = n & (HD_ - 1);
                if (z == 2) {
                    // V transposed: [B,H,HD,S]
                    {
                        const int b_ = m >> 11, s_ = m & (S_ - 1);
                        __half* base = g_Vt + (((size_t)b_ * H_ + h_) * HD_ + d_) * S_ + s_;
                        base[0]  = __float2half_rn(v00);
                        base[S_] = __float2half_rn(v01);
                    }
                    {
                        const int m2 = m + 8;
                        const int b_ = m2 >> 11, s_ = m2 & (S_ - 1);
                        __half* base = g_Vt + (((size_t)b_ * H_ + h_) * HD_ + d_) * S_ + s_;
                        base[0]  = __float2half_rn(v10);
                        base[S_] = __float2half_rn(v11);
                    }
                } else {
                    __half* dst = (z == 0) ? g_Q : g_K;
                    {
                        const int b_ = m >> 11, s_ = m & (S_ - 1);
                        *(uint32_t*)(dst + (((size_t)b_ * H_ + h_) * S_ + s_) * HD_ + d_) =
                            pk2(v00, v01);
                    }
                    {
                        const int m2 = m + 8;
                        const int b_ = m2 >> 11, s_ = m2 & (S_ - 1);
                        *(uint32_t*)(dst + (((size_t)b_ * H_ + h_) * S_ + s_) * HD_ + d_) =
                            pk2(v10, v11);
                    }
                }
            }
        }
    }
}

// ---------------------------------------------------------------------------
// Flash attention, softmax-one, fp16 mma (fp32 accum/softmax), cp.async
// double-buffered K/Vt, occ 2, ldmatrix for Q/K/P/V frags.
// Q pre-scaled by 0.125 in projection. O^T = V^T @ P^T. Bc=64 as two chunks.
// smem (halves): Qs 128x72 (reused as Ps), Ks[2][64][72], Vts[2][64][72].
// ---------------------------------------------------------------------------
#define KVB (64 * LDH * 2)   // bytes per K or V buffer = 9216

__global__ __launch_bounds__(256, 2)
void attn_f16()
{
    extern __shared__ __half smh[];
    __half* Qs = smh;                           // 128*72 halves
    const uint32_t sQ = (uint32_t)__cvta_generic_to_shared(Qs);
    const uint32_t sK = sQ + 128 * LDH * 2;     // [2][64][72]
    const uint32_t sV = sK + 2 * KVB;           // [2][64][72]

    const int tid  = threadIdx.x;
    const int warp = tid >> 5, lane = tid & 31;
    const int g = lane >> 2, tg = lane & 3;
    const int bh = blockIdx.y;
    const int q0blk = blockIdx.x * 128;
    const int b = bh >> 4, h = bh & (H_ - 1);

    const __half* Qg  = g_Q + ((size_t)bh * S_ + q0blk) * HD_;
    const __half* Kg  = g_K + (size_t)bh * S_ * HD_;
    const __half* Vtg = g_Vt + (size_t)bh * HD_ * S_;

    // fragment bases (halves)
    const int q_base  = (warp * 16 + (lane & 15)) * LDH + ((lane >> 4) << 3);
    const int k_base  = (((lane >> 4) << 3) + (lane & 7)) * LDH
                      + (((lane >> 3) & 1) << 3);
    const int p_base  = q_base;                      // same pattern, Ps reuses Qs
    const int vt_base = (lane & 15) * LDH + ((lane >> 4) << 3);

    // prefetch K/Vt tile 0 (64 rows x 64 halves each = 512 chunks of 16B)
#pragma unroll
    for (int i = 0; i < 2; i++) {
        const int f = tid + 256 * i;
        const int row = f >> 3, ch = (f & 7) << 3;
        const uint32_t off = (uint32_t)(row * LDH + ch) << 1;
        cpa16(sK + off, Kg + (size_t)row * HD_ + ch);
        cpa16(sV + off, Vtg + (size_t)row * S_ + ch);
    }
    CP_COMMIT();

    // stage Q tile (plain 16B loads)
#pragma unroll
    for (int i = 0; i < 4; i++) {
        const int f = tid + 256 * i;
        const int row = f >> 3, ch = (f & 7) << 3;
        *(uint4*)((char*)Qs + ((size_t)(row * LDH + ch) << 1)) =
            *(const uint4*)(Qg + (size_t)row * HD_ + ch);
    }
    __syncthreads();

    uint32_t qf[4][4];
#pragma unroll
    for (int ks = 0; ks < 4; ks++)
        ldsm4(qf[ks], sQ + ((uint32_t)(q_base + ks * 16) << 1));
    __syncthreads();   // Qs now reusable as Ps

    float oacc[4][2][4];
#pragma unroll
    for (int i = 0; i < 4; i++)
#pragma unroll
        for (int j = 0; j < 2; j++)
#pragma unroll
            for (int k = 0; k < 4; k++) oacc[i][j][k] = 0.0f;

    float m0 = 0.0f, m1 = 0.0f;   // virtual zero logit
    float l0 = 1.0f, l1 = 1.0f;

    const int qrow = warp * 16 + g;

    for (int t = 0; t < 32; t++) {
        CP_WAIT0();
        __syncthreads();

        if (t + 1 < 32) {
            const size_t gofs = (size_t)(t + 1) * 64;
            const uint32_t bK = (uint32_t)(((t + 1) & 1) * KVB);
            const uint32_t bV = (uint32_t)(((t + 1) & 1) * KVB);
#pragma unroll
            for (int i = 0; i < 2; i++) {
                const int f = tid + 256 * i;
                const int row = f >> 3, ch = (f & 7) << 3;
                const uint32_t off = (uint32_t)(row * LDH + ch) << 1;
                cpa16(sK + bK + off, Kg + (gofs + row) * HD_ + ch);
                cpa16(sV + bV + off, Vtg + (size_t)row * S_ + gofs + ch);
            }
            CP_COMMIT();
        }

        const uint32_t sKb = sK + (uint32_t)((t & 1) * KVB);
        const uint32_t sVb = sV + (uint32_t)((t & 1) * KVB);

#pragma unroll
        for (int c = 0; c < 2; c++) {
            const int colbase = c * 32;
            float s[4][4];
#pragma unroll
            for (int nt = 0; nt < 4; nt++)
                s[nt][0] = s[nt][1] = s[nt][2] = s[nt][3] = 0.0f;

            // S chunk = Q @ K^T  (4 ksteps of k16)
#pragma unroll
            for (int ks = 0; ks < 4; ks++) {
#pragma unroll
                for (int p = 0; p < 2; p++) {
                    uint32_t kf[4];
                    ldsm4(kf, sKb + ((uint32_t)(k_base + (colbase + p * 16) * LDH
                                                + ks * 16) << 1));
                    mma_f16(s[2 * p],     qf[ks][0], qf[ks][1], qf[ks][2], qf[ks][3],
                            kf[0], kf[1]);
                    mma_f16(s[2 * p + 1], qf[ks][0], qf[ks][1], qf[ks][2], qf[ks][3],
                            kf[2], kf[3]);
                }
            }

            // online softmax-one update
            float rm0 = m0, rm1 = m1;
#pragma unroll
            for (int nt = 0; nt < 4; nt++) {
                rm0 = fmaxf(rm0, fmaxf(s[nt][0], s[nt][1]));
                rm1 = fmaxf(rm1, fmaxf(s[nt][2], s[nt][3]));
            }
            rm0 = fmaxf(rm0, __shfl_xor_sync(0xffffffffu, rm0, 1));
            rm0 = fmaxf(rm0, __shfl_xor_sync(0xffffffffu, rm0, 2));
            rm1 = fmaxf(rm1, __shfl_xor_sync(0xffffffffu, rm1, 1));
            rm1 = fmaxf(rm1, __shfl_xor_sync(0xffffffffu, rm1, 2));

            const float corr0 = __expf(m0 - rm0);
            const float corr1 = __expf(m1 - rm1);

            float ls0 = 0.0f, ls1 = 0.0f;
#pragma unroll
            for (int nt = 0; nt < 4; nt++) {
                const float p00 = __expf(s[nt][0] - rm0);
                const float p01 = __expf(s[nt][1] - rm0);
                const float p10 = __expf(s[nt][2] - rm1);
                const float p11 = __expf(s[nt][3] - rm1);
                ls0 += p00 + p01;
                ls1 += p10 + p11;
                const int col = colbase + nt * 8 + 2 * tg;
                *(uint32_t*)&Qs[qrow * LDH + col]       = pk2(p00, p01);
                *(uint32_t*)&Qs[(qrow + 8) * LDH + col] = pk2(p10, p11);
            }
            ls0 += __shfl_xor_sync(0xffffffffu, ls0, 1);
            ls0 += __shfl_xor_sync(0xffffffffu, ls0, 2);
            ls1 += __shfl_xor_sync(0xffffffffu, ls1, 1);
            ls1 += __shfl_xor_sync(0xffffffffu, ls1, 2);
            l0 = l0 * corr0 + ls0; m0 = rm0;
            l1 = l1 * corr1 + ls1; m1 = rm1;
            __syncwarp();

            // rescale O^T accumulators (corr per q-column via shuffle)
#pragma unroll
            for (int nt = 0; nt < 2; nt++) {
                const int ql0 = 2 * tg, ql1 = 2 * tg + 1;
                float c0a = __shfl_sync(0xffffffffu, corr0, ql0 * 4);
                float c0b = __shfl_sync(0xffffffffu, corr1, ql0 * 4);
                float c1a = __shfl_sync(0xffffffffu, corr0, ql1 * 4);
                float c1b = __shfl_sync(0xffffffffu, corr1, ql1 * 4);
                const float cq0 = (nt == 0) ? c0a : c0b;
                const float cq1 = (nt == 0) ? c1a : c1b;
#pragma unroll
                for (int dt = 0; dt < 4; dt++) {
                    oacc[dt][nt][0] *= cq0;
                    oacc[dt][nt][1] *= cq1;
                    oacc[dt][nt][2] *= cq0;
                    oacc[dt][nt][3] *= cq1;
                }
            }

            // O^T += V^T @ P^T  (2 ksteps of k16 per 32-chunk)
#pragma unroll
            for (int ks2 = 0; ks2 < 2; ks2++) {
                const int kk = colbase + ks2 * 16;
                uint32_t pr[4];
                ldsm4(pr, sQ + ((uint32_t)(p_base + kk) << 1));
#pragma unroll
                for (int dt = 0; dt < 4; dt++) {
                    uint32_t vf[4];
                    ldsm4(vf, sVb + ((uint32_t)(vt_base + dt * 16 * LDH + kk) << 1));
                    mma_f16(oacc[dt][0], vf[0], vf[1], vf[2], vf[3], pr[0], pr[2]);
                    mma_f16(oacc[dt][1], vf[0], vf[1], vf[2], vf[3], pr[1], pr[3]);
                }
            }
        }
    }

    // finalize: divide by l (per q-row), fp16-round, store O^T frags to g_O
    const float inv0 = 1.0f / l0;
    const float inv1 = 1.0f / l1;
    float ivq[2][2];
#pragma unroll
    for (int nt = 0; nt < 2; nt++) {
        const int ql0 = 2 * tg, ql1 = 2 * tg + 1;
        float a0 = __shfl_sync(0xffffffffu, inv0, ql0 * 4);
        float b0 = __shfl_sync(0xffffffffu, inv1, ql0 * 4);
        float a1 = __shfl_sync(0xffffffffu, inv0, ql1 * 4);
        float b1 = __shfl_sync(0xffffffffu, inv1, ql1 * 4);
        ivq[nt][0] = (nt == 0) ? a0 : b0;
        ivq[nt][1] = (nt == 0) ? a1 : b1;
    }

    const size_t obase = ((size_t)(b * S_ + q0blk + warp * 16)) * DM_ + h * HD_;
#pragma unroll
    for (int dt = 0; dt < 4; dt++) {
#pragma unroll
        for (int nt = 0; nt < 2; nt++) {
            const int d  = dt * 16 + g;
            const int ql = nt * 8 + 2 * tg;
            g_O[obase + (size_t)ql * DM_ + d]           = __float2half_rn(oacc[dt][nt][0] * ivq[nt][0]);
            g_O[obase + (size_t)(ql + 1) * DM_ + d]     = __float2half_rn(oacc[dt][nt][1] * ivq[nt][1]);
            g_O[obase + (size_t)ql * DM_ + d + 8]       = __float2half_rn(oacc[dt][nt][2] * ivq[nt][0]);
            g_O[obase + (size_t)(ql + 1) * DM_ + d + 8] = __float2half_rn(oacc[dt][nt][3] * ivq[nt][1]);
        }
    }
}

// ---------------------------------------------------------------------------
// Launch (only harness pointers cross the host/device boundary)
// ---------------------------------------------------------------------------
extern "C" void kernel_launch(void* const* d_in, const int* in_sizes, int n_in,
                              void* d_out, int out_size)
{
    const float* query = (const float*)d_in[0];
    const float* key   = (const float*)d_in[1];
    const float* value = (const float*)d_in[2];
    const float* bq = (const float*)d_in[4];
    const float* bk = (const float*)d_in[6];
    const float* bv = (const float*)d_in[8];
    const float* bo = (const float*)d_in[10];
    float* out = (float*)d_out;

    const int gemm_smem = 4 * GTILEB;                 // 73728
    const int attn_smem = 128 * LDH * 2 + 4 * KVB;    // 18432 + 36864 = 55296

    cudaFuncSetAttribute(gemm_f16<0>, cudaFuncAttributeMaxDynamicSharedMemorySize, gemm_smem);
    cudaFuncSetAttribute(gemm_f16<1>, cudaFuncAttributeMaxDynamicSharedMemorySize, gemm_smem);
    cudaFuncSetAttribute(attn_f16, cudaFuncAttributeMaxDynamicSharedMemorySize, attn_smem);

    prep_half<<<dim3(1024, 7), 256>>>(query, key, value,
                                      (const float*)d_in[3], (const float*)d_in[5],
                                      (const float*)d_in[7], (const float*)d_in[9]);

    // merged QKV projections: grid.z selects q/k/v
    gemm_f16<1><<<dim3(DM_ / 128, MTOT / 128, 3), 256, gemm_smem>>>(bq, bk, bv, nullptr);

    attn_f16<<<dim3(S_ / 128, B_ * H_), 256, attn_smem>>>();

    gemm_f16<0><<<dim3(DM_ / 128, MTOT / 128, 1), 256, gemm_smem>>>(bo, nullptr, nullptr, out);
}

// round 12
// speedup vs baseline: 7.8157x; 1.0222x over previous
#include <cuda_runtime.h>
#include <cuda_fp16.h>
#include <cstdint>
#include <math.h>

#define B_ 2
#define S_ 2048
#define DM_ 1024
#define H_ 16
#define HD_ 64
#define MTOT (B_ * S_)      // 4096
// 0.125 * log2(e): folded into Q projection so softmax runs in exp2 domain
#define QSCALE 0.18033688f

#define fu __float_as_uint
#define uf __uint_as_float

// Scratch (allocation-free: __device__ globals; referenced ONLY in device code)
__device__ __half g_Q[(size_t)B_ * H_ * S_ * HD_];   // [B,H,S,HD], fp16, pre-scaled
__device__ __half g_K[(size_t)B_ * H_ * S_ * HD_];   // [B,H,S,HD], fp16
__device__ __half g_Vt[(size_t)B_ * H_ * HD_ * S_];  // [B,H,HD,S] TRANSPOSED, fp16
__device__ __half g_O[(size_t)B_ * S_ * DM_];        // [B*S,DM], fp16
__device__ __half g_Xq[(size_t)MTOT * DM_];          // fp16 inputs
__device__ __half g_Xk[(size_t)MTOT * DM_];
__device__ __half g_Xv[(size_t)MTOT * DM_];
__device__ __half g_Wq[(size_t)DM_ * DM_];           // fp16 weights
__device__ __half g_Wk[(size_t)DM_ * DM_];
__device__ __half g_Wv[(size_t)DM_ * DM_];
__device__ __half g_Wo[(size_t)DM_ * DM_];

__device__ __forceinline__ uint32_t pk2(float a, float b) {
    __half2 h = __floats2half2_rn(a, b);
    return *reinterpret_cast<uint32_t*>(&h);
}

__device__ __forceinline__ float ex2(float x) {
    float r;
    asm("ex2.approx.ftz.f32 %0, %1;" : "=f"(r) : "f"(x));
    return r;
}

__device__ __forceinline__ void mma_f16(float c[4],
                                        uint32_t a0, uint32_t a1, uint32_t a2, uint32_t a3,
                                        uint32_t b0, uint32_t b1) {
    asm volatile(
        "mma.sync.aligned.m16n8k16.row.col.f32.f16.f16.f32 "
        "{%0,%1,%2,%3}, {%4,%5,%6,%7}, {%8,%9}, {%0,%1,%2,%3};\n"
        : "+f"(c[0]), "+f"(c[1]), "+f"(c[2]), "+f"(c[3])
        : "r"(a0), "r"(a1), "r"(a2), "r"(a3), "r"(b0), "r"(b1));
}

__device__ __forceinline__ void ldsm4(uint32_t r[4], uint32_t addr) {
    asm volatile("ldmatrix.sync.aligned.m8n8.x4.shared.b16 {%0,%1,%2,%3}, [%4];"
                 : "=r"(r[0]), "=r"(r[1]), "=r"(r[2]), "=r"(r[3]) : "r"(addr));
}

__device__ __forceinline__ void cpa16(uint32_t dst, const void* src) {
    asm volatile("cp.async.cg.shared.global [%0], [%1], 16;" :: "r"(dst), "l"(src));
}
#define CP_COMMIT() asm volatile("cp.async.commit_group;")
#define CP_WAIT0()  asm volatile("cp.async.wait_group 0;")

// ---------------------------------------------------------------------------
// Prep: convert inputs and weights to fp16 (rn) once (elementwise).
// ---------------------------------------------------------------------------
__global__ void prep_half(const float* __restrict__ q, const float* __restrict__ k,
                          const float* __restrict__ v, const float* __restrict__ wq,
                          const float* __restrict__ wk, const float* __restrict__ wv,
                          const float* __restrict__ wo)
{
    const float* src; __half* dst; int n;
    switch (blockIdx.y) {
        case 0: src = q;  dst = g_Xq; n = MTOT * DM_; break;
        case 1: src = k;  dst = g_Xk; n = MTOT * DM_; break;
        case 2: src = v;  dst = g_Xv; n = MTOT * DM_; break;
        case 3: src = wq; dst = g_Wq; n = DM_ * DM_;  break;
        case 4: src = wk; dst = g_Wk; n = DM_ * DM_;  break;
        case 5: src = wv; dst = g_Wv; n = DM_ * DM_;  break;
        default: src = wo; dst = g_Wo; n = DM_ * DM_; break;
    }
    const int n8 = n >> 3;
    for (int i = blockIdx.x * blockDim.x + threadIdx.x; i < n8;
         i += gridDim.x * blockDim.x) {
        float4 x0 = ((const float4*)src)[2 * i];
        float4 x1 = ((const float4*)src)[2 * i + 1];
        uint4 o;
        o.x = pk2(x0.x, x0.y); o.y = pk2(x0.z, x0.w);
        o.z = pk2(x1.x, x1.y); o.w = pk2(x1.z, x1.w);
        ((uint4*)dst)[i] = o;
    }
}

// ---------------------------------------------------------------------------
// fp16 GEMM (persistent): Y[m,n] = sum_k X[m,k]*W[n,k] + bias[n]
// cp.async double-buffered tiles, DOUBLE-BUFFERED FRAGMENTS across k-steps,
// single sync per k-tile. Tiles 128x128, BK=64 halves, ld=72 halves.
// MODE 0: X=g_O, W=g_Wo -> fp32 out (256 items). MODE 1: merged QKV, 768
// items, z=item>>8 (z==0 Q scaled by QSCALE; z==2 V transposed into g_Vt).
// ---------------------------------------------------------------------------
#define LDH 72
#define GTILEB (128 * LDH * 2)   // bytes per matrix buffer = 18432

template <int MODE>
__global__ __launch_bounds__(256, 2)
void gemm_f16(const float* __restrict__ bias0, const float* __restrict__ bias1,
              const float* __restrict__ bias2, float* __restrict__ Y)
{
    extern __shared__ __half smh[];
    const uint32_t sA = (uint32_t)__cvta_generic_to_shared(smh);
    const uint32_t sB = sA + GTILEB;

    const int tid  = threadIdx.x;
    const int warp = tid >> 5, lane = tid & 31;
    const int g  = lane >> 2, tg = lane & 3;
    const int wm = warp >> 2, wn = warp & 3;

    const int a_base = (wm * 64 + (lane & 15)) * LDH + ((lane >> 4) << 3);
    const int b_base = (wn * 32 + ((lane >> 4) << 3) + (lane & 7)) * LDH
                     + (((lane >> 3) & 1) << 3);

    const int NITEMS = (MODE == 0) ? 256 : 768;

    for (int item = blockIdx.x; item < NITEMS; item += gridDim.x) {
        const int z = (MODE == 0) ? 0 : (item >> 8);
        const int rem = item & 255;
        const int bn = (rem & 7) * 128;
        const int bm = (rem >> 3) * 128;

        const __half* X = (MODE == 0) ? g_O : (z == 0) ? g_Xq : (z == 1) ? g_Xk : g_Xv;
        const __half* W = (MODE == 0) ? g_Wo : (z == 0) ? g_Wq : (z == 1) ? g_Wk : g_Wv;
        const float* bias = (MODE == 0) ? bias0 : (z == 0) ? bias0 : (z == 1) ? bias1 : bias2;

        float acc[4][4][4];
#pragma unroll
        for (int i = 0; i < 4; i++)
#pragma unroll
            for (int j = 0; j < 4; j++)
#pragma unroll
                for (int k = 0; k < 4; k++) acc[i][j][k] = 0.0f;

        // prefetch tile 0
#pragma unroll
        for (int i = 0; i < 4; i++) {
            const int f = tid + 256 * i;
            const int row = f >> 3, ch = (f & 7) << 3;
            const uint32_t off = (uint32_t)(row * LDH + ch) << 1;
            cpa16(sA + off, X + (size_t)(bm + row) * DM_ + ch);
            cpa16(sB + off, W + (size_t)(bn + row) * DM_ + ch);
        }
        CP_COMMIT();

        for (int t = 0; t < 16; t++) {
            CP_WAIT0();
            __syncthreads();

            if (t + 1 < 16) {
                const int k0 = (t + 1) * 64;
                const uint32_t bufo = (uint32_t)(((t + 1) & 1) * 2 * GTILEB);
#pragma unroll
                for (int i = 0; i < 4; i++) {
                    const int f = tid + 256 * i;
                    const int row = f >> 3, ch = (f & 7) << 3;
                    const uint32_t off = bufo + ((uint32_t)(row * LDH + ch) << 1);
                    cpa16(sA + off, X + (size_t)(bm + row) * DM_ + k0 + ch);
                    cpa16(sB + off, W + (size_t)(bn + row) * DM_ + k0 + ch);
                }
                CP_COMMIT();
            }

            const uint32_t bufb = (uint32_t)((t & 1) * 2 * GTILEB);
            const uint32_t sAb = sA + bufb;
            const uint32_t sBb = sB + bufb;

            // double-buffered fragments across k-steps
            uint32_t af[2][4][4], bf[2][2][4];
#pragma unroll
            for (int mi = 0; mi < 4; mi++)
                ldsm4(af[0][mi], sAb + ((uint32_t)(a_base + mi * 16 * LDH) << 1));
#pragma unroll
            for (int p = 0; p < 2; p++)
                ldsm4(bf[0][p], sBb + ((uint32_t)(b_base + p * 16 * LDH) << 1));

#pragma unroll
            for (int ks = 0; ks < 4; ks++) {
                const int cur = ks & 1, nxt = cur ^ 1;
                if (ks < 3) {
                    const int kk = (ks + 1) * 16;
#pragma unroll
                    for (int mi = 0; mi < 4; mi++)
                        ldsm4(af[nxt][mi],
                              sAb + ((uint32_t)(a_base + mi * 16 * LDH + kk) << 1));
#pragma unroll
                    for (int p = 0; p < 2; p++)
                        ldsm4(bf[nxt][p],
                              sBb + ((uint32_t)(b_base + p * 16 * LDH + kk) << 1));
                }
#pragma unroll
                for (int mi = 0; mi < 4; mi++)
#pragma unroll
                    for (int p = 0; p < 2; p++) {
                        mma_f16(acc[mi][2 * p],
                                af[cur][mi][0], af[cur][mi][1], af[cur][mi][2], af[cur][mi][3],
                                bf[cur][p][0], bf[cur][p][1]);
                        mma_f16(acc[mi][2 * p + 1],
                                af[cur][mi][0], af[cur][mi][1], af[cur][mi][2], af[cur][mi][3],
                                bf[cur][p][2], bf[cur][p][3]);
                    }
            }
        }
        __syncthreads();   // all warps done with smem before next item's prefetch

        // epilogue
#pragma unroll
        for (int mi = 0; mi < 4; mi++) {
#pragma unroll
            for (int ni = 0; ni < 4; ni++) {
                const int m = bm + wm * 64 + mi * 16 + g;
                const int n = bn + wn * 32 + ni * 8 + 2 * tg;
                const float b0 = bias[n], b1 = bias[n + 1];
                float v00 = acc[mi][ni][0] + b0;
                float v01 = acc[mi][ni][1] + b1;
                float v10 = acc[mi][ni][2] + b0;
                float v11 = acc[mi][ni][3] + b1;
                if (MODE == 0) {
                    *(float2*)(Y + (size_t)m * DM_ + n)       = make_float2(v00, v01);
                    *(float2*)(Y + (size_t)(m + 8) * DM_ + n) = make_float2(v10, v11);
                } else {
                    if (z == 0) { v00 *= QSCALE; v01 *= QSCALE; v10 *= QSCALE; v11 *= QSCALE; }
                    const int h_ = n >> 6, d_ = n & (HD_ - 1);
                    if (z == 2) {
                        {
                            const int b_ = m >> 11, s_ = m & (S_ - 1);
                            __half* base = g_Vt + (((size_t)b_ * H_ + h_) * HD_ + d_) * S_ + s_;
                            base[0]  = __float2half_rn(v00);
                            base[S_] = __float2half_rn(v01);
                        }
                        {
                            const int m2 = m + 8;
                            const int b_ = m2 >> 11, s_ = m2 & (S_ - 1);
                            __half* base = g_Vt + (((size_t)b_ * H_ + h_) * HD_ + d_) * S_ + s_;
                            base[0]  = __float2half_rn(v10);
                            base[S_] = __float2half_rn(v11);
                        }
                    } else {
                        __half* dst = (z == 0) ? g_Q : g_K;
                        {
                            const int b_ = m >> 11, s_ = m & (S_ - 1);
                            *(uint32_t*)(dst + (((size_t)b_ * H_ + h_) * S_ + s_) * HD_ + d_) =
                                pk2(v00, v01);
                        }
                        {
                            const int m2 = m + 8;
                            const int b_ = m2 >> 11, s_ = m2 & (S_ - 1);
                            *(uint32_t*)(dst + (((size_t)b_ * H_ + h_) * S_ + s_) * HD_ + d_) =
                                pk2(v10, v11);
                        }
                    }
                }
            }
        }
    }
}

// ---------------------------------------------------------------------------
// Flash attention (persistent): softmax-one in exp2 domain, fp16 mma,
// cp.async double-buffered K/Vt, occ 2, ldmatrix Q/K/P/V frags.
// 512 items = 16 q-tiles x 32 bh. O^T = V^T @ P^T.
// ---------------------------------------------------------------------------
#define KVB (64 * LDH * 2)   // 9216

__global__ __launch_bounds__(256, 2)
void attn_f16()
{
    extern __shared__ __half smh[];
    __half* Qs = smh;                           // 128*72 halves (reused as Ps)
    const uint32_t sQ = (uint32_t)__cvta_generic_to_shared(Qs);
    const uint32_t sK = sQ + 128 * LDH * 2;
    const uint32_t sV = sK + 2 * KVB;

    const int tid  = threadIdx.x;
    const int warp = tid >> 5, lane = tid & 31;
    const int g = lane >> 2, tg = lane & 3;

    const int q_base  = (warp * 16 + (lane & 15)) * LDH + ((lane >> 4) << 3);
    const int k_base  = (((lane >> 4) << 3) + (lane & 7)) * LDH
                      + (((lane >> 3) & 1) << 3);
    const int p_base  = q_base;
    const int vt_base = (lane & 15) * LDH + ((lane >> 4) << 3);
    const int qrow = warp * 16 + g;

    for (int item = blockIdx.x; item < 512; item += gridDim.x) {
        const int bh = item & 31;
        const int q0blk = (item >> 5) * 128;
        const int b = bh >> 4, h = bh & (H_ - 1);

        const __half* Qg  = g_Q + ((size_t)bh * S_ + q0blk) * HD_;
        const __half* Kg  = g_K + (size_t)bh * S_ * HD_;
        const __half* Vtg = g_Vt + (size_t)bh * HD_ * S_;

        // prefetch K/Vt tile 0
#pragma unroll
        for (int i = 0; i < 2; i++) {
            const int f = tid + 256 * i;
            const int row = f >> 3, ch = (f & 7) << 3;
            const uint32_t off = (uint32_t)(row * LDH + ch) << 1;
            cpa16(sK + off, Kg + (size_t)row * HD_ + ch);
            cpa16(sV + off, Vtg + (size_t)row * S_ + ch);
        }
        CP_COMMIT();

        // stage Q tile
#pragma unroll
        for (int i = 0; i < 4; i++) {
            const int f = tid + 256 * i;
            const int row = f >> 3, ch = (f & 7) << 3;
            *(uint4*)((char*)Qs + ((size_t)(row * LDH + ch) << 1)) =
                *(const uint4*)(Qg + (size_t)row * HD_ + ch);
        }
        __syncthreads();

        uint32_t qf[4][4];
#pragma unroll
        for (int ks = 0; ks < 4; ks++)
            ldsm4(qf[ks], sQ + ((uint32_t)(q_base + ks * 16) << 1));
        __syncthreads();   // Qs now reusable as Ps

        float oacc[4][2][4];
#pragma unroll
        for (int i = 0; i < 4; i++)
#pragma unroll
            for (int j = 0; j < 2; j++)
#pragma unroll
                for (int k = 0; k < 4; k++) oacc[i][j][k] = 0.0f;

        float m0 = 0.0f, m1 = 0.0f;   // virtual zero logit (log2 domain)
        float l0 = 1.0f, l1 = 1.0f;

        for (int t = 0; t < 32; t++) {
            CP_WAIT0();
            __syncthreads();

            if (t + 1 < 32) {
                const size_t gofs = (size_t)(t + 1) * 64;
                const uint32_t bK = (uint32_t)(((t + 1) & 1) * KVB);
#pragma unroll
                for (int i = 0; i < 2; i++) {
                    const int f = tid + 256 * i;
                    const int row = f >> 3, ch = (f & 7) << 3;
                    const uint32_t off = (uint32_t)(row * LDH + ch) << 1;
                    cpa16(sK + bK + off, Kg + (gofs + row) * HD_ + ch);
                    cpa16(sV + bK + off, Vtg + (size_t)row * S_ + gofs + ch);
                }
                CP_COMMIT();
            }

            const uint32_t sKb = sK + (uint32_t)((t & 1) * KVB);
            const uint32_t sVb = sV + (uint32_t)((t & 1) * KVB);

#pragma unroll
            for (int c = 0; c < 2; c++) {
                const int colbase = c * 32;
                float s[4][4];
#pragma unroll
                for (int nt = 0; nt < 4; nt++)
                    s[nt][0] = s[nt][1] = s[nt][2] = s[nt][3] = 0.0f;

#pragma unroll
                for (int ks = 0; ks < 4; ks++) {
#pragma unroll
                    for (int p = 0; p < 2; p++) {
                        uint32_t kf[4];
                        ldsm4(kf, sKb + ((uint32_t)(k_base + (colbase + p * 16) * LDH
                                                    + ks * 16) << 1));
                        mma_f16(s[2 * p],     qf[ks][0], qf[ks][1], qf[ks][2], qf[ks][3],
                                kf[0], kf[1]);
                        mma_f16(s[2 * p + 1], qf[ks][0], qf[ks][1], qf[ks][2], qf[ks][3],
                                kf[2], kf[3]);
                    }
                }

                float rm0 = m0, rm1 = m1;
#pragma unroll
                for (int nt = 0; nt < 4; nt++) {
                    rm0 = fmaxf(rm0, fmaxf(s[nt][0], s[nt][1]));
                    rm1 = fmaxf(rm1, fmaxf(s[nt][2], s[nt][3]));
                }
                rm0 = fmaxf(rm0, __shfl_xor_sync(0xffffffffu, rm0, 1));
                rm0 = fmaxf(rm0, __shfl_xor_sync(0xffffffffu, rm0, 2));
                rm1 = fmaxf(rm1, __shfl_xor_sync(0xffffffffu, rm1, 1));
                rm1 = fmaxf(rm1, __shfl_xor_sync(0xffffffffu, rm1, 2));

                const float corr0 = ex2(m0 - rm0);
                const float corr1 = ex2(m1 - rm1);

                float ls0 = 0.0f, ls1 = 0.0f;
#pragma unroll
                for (int nt = 0; nt < 4; nt++) {
                    const float p00 = ex2(s[nt][0] - rm0);
                    const float p01 = ex2(s[nt][1] - rm0);
                    const float p10 = ex2(s[nt][2] - rm1);
                    const float p11 = ex2(s[nt][3] - rm1);
                    ls0 += p00 + p01;
                    ls1 += p10 + p11;
                    const int col = colbase + nt * 8 + 2 * tg;
                    *(uint32_t*)&Qs[qrow * LDH + col]       = pk2(p00, p01);
                    *(uint32_t*)&Qs[(qrow + 8) * LDH + col] = pk2(p10, p11);
                }
                ls0 += __shfl_xor_sync(0xffffffffu, ls0, 1);
                ls0 += __shfl_xor_sync(0xffffffffu, ls0, 2);
                ls1 += __shfl_xor_sync(0xffffffffu, ls1, 1);
                ls1 += __shfl_xor_sync(0xffffffffu, ls1, 2);
                l0 = l0 * corr0 + ls0; m0 = rm0;
                l1 = l1 * corr1 + ls1; m1 = rm1;
                __syncwarp();

#pragma unroll
                for (int nt = 0; nt < 2; nt++) {
                    const int ql0 = 2 * tg, ql1 = 2 * tg + 1;
                    float c0a = __shfl_sync(0xffffffffu, corr0, ql0 * 4);
                    float c0b = __shfl_sync(0xffffffffu, corr1, ql0 * 4);
                    float c1a = __shfl_sync(0xffffffffu, corr0, ql1 * 4);
                    float c1b = __shfl_sync(0xffffffffu, corr1, ql1 * 4);
                    const float cq0 = (nt == 0) ? c0a : c0b;
                    const float cq1 = (nt == 0) ? c1a : c1b;
#pragma unroll
                    for (int dt = 0; dt < 4; dt++) {
                        oacc[dt][nt][0] *= cq0;
                        oacc[dt][nt][1] *= cq1;
                        oacc[dt][nt][2] *= cq0;
                        oacc[dt][nt][3] *= cq1;
                    }
                }

#pragma unroll
                for (int ks2 = 0; ks2 < 2; ks2++) {
                    const int kk = colbase + ks2 * 16;
                    uint32_t pr[4];
                    ldsm4(pr, sQ + ((uint32_t)(p_base + kk) << 1));
#pragma unroll
                    for (int dt = 0; dt < 4; dt++) {
                        uint32_t vf[4];
                        ldsm4(vf, sVb + ((uint32_t)(vt_base + dt * 16 * LDH + kk) << 1));
                        mma_f16(oacc[dt][0], vf[0], vf[1], vf[2], vf[3], pr[0], pr[2]);
                        mma_f16(oacc[dt][1], vf[0], vf[1], vf[2], vf[3], pr[1], pr[3]);
                    }
                }
            }
        }

        // finalize: divide by l, store O^T frags (fp16) to g_O
        const float inv0 = 1.0f / l0;
        const float inv1 = 1.0f / l1;
        float ivq[2][2];
#pragma unroll
        for (int nt = 0; nt < 2; nt++) {
            const int ql0 = 2 * tg, ql1 = 2 * tg + 1;
            float a0 = __shfl_sync(0xffffffffu, inv0, ql0 * 4);
            float b0 = __shfl_sync(0xffffffffu, inv1, ql0 * 4);
            float a1 = __shfl_sync(0xffffffffu, inv0, ql1 * 4);
            float b1 = __shfl_sync(0xffffffffu, inv1, ql1 * 4);
            ivq[nt][0] = (nt == 0) ? a0 : b0;
            ivq[nt][1] = (nt == 0) ? a1 : b1;
        }

        const size_t obase = ((size_t)(b * S_ + q0blk + warp * 16)) * DM_ + h * HD_;
#pragma unroll
        for (int dt = 0; dt < 4; dt++) {
#pragma unroll
            for (int nt = 0; nt < 2; nt++) {
                const int d  = dt * 16 + g;
                const int ql = nt * 8 + 2 * tg;
                g_O[obase + (size_t)ql * DM_ + d]           = __float2half_rn(oacc[dt][nt][0] * ivq[nt][0]);
                g_O[obase + (size_t)(ql + 1) * DM_ + d]     = __float2half_rn(oacc[dt][nt][1] * ivq[nt][1]);
                g_O[obase + (size_t)ql * DM_ + d + 8]       = __float2half_rn(oacc[dt][nt][2] * ivq[nt][0]);
                g_O[obase + (size_t)(ql + 1) * DM_ + d + 8] = __float2half_rn(oacc[dt][nt][3] * ivq[nt][1]);
            }
        }
        __syncthreads();   // smem safe to reuse for next item
    }
}

// ---------------------------------------------------------------------------
// Launch (only harness pointers cross the host/device boundary)
// ---------------------------------------------------------------------------
extern "C" void kernel_launch(void* const* d_in, const int* in_sizes, int n_in,
                              void* d_out, int out_size)
{
    const float* query = (const float*)d_in[0];
    const float* key   = (const float*)d_in[1];
    const float* value = (const float*)d_in[2];
    const float* bq = (const float*)d_in[4];
    const float* bk = (const float*)d_in[6];
    const float* bv = (const float*)d_in[8];
    const float* bo = (const float*)d_in[10];
    float* out = (float*)d_out;

    const int gemm_smem = 4 * GTILEB;                 // 73728
    const int attn_smem = 128 * LDH * 2 + 4 * KVB;    // 55296
    const int PGRID = 296;                            // 2 CTAs/SM x 148 SMs

    cudaFuncSetAttribute(gemm_f16<0>, cudaFuncAttributeMaxDynamicSharedMemorySize, gemm_smem);
    cudaFuncSetAttribute(gemm_f16<1>, cudaFuncAttributeMaxDynamicSharedMemorySize, gemm_smem);
    cudaFuncSetAttribute(attn_f16, cudaFuncAttributeMaxDynamicSharedMemorySize, attn_smem);

    prep_half<<<dim3(1024, 7), 256>>>(query, key, value,
                                      (const float*)d_in[3], (const float*)d_in[5],
                                      (const float*)d_in[7], (const float*)d_in[9]);

    // merged QKV projections: 768 items on a persistent grid
    gemm_f16<1><<<PGRID, 256, gemm_smem>>>(bq, bk, bv, nullptr);

    // attention: 512 items on a persistent grid
    attn_f16<<<PGRID, 256, attn_smem>>>();

    // output projection: 256 items (single wave)
    gemm_f16<0><<<256, 256, gemm_smem>>>(bo, nullptr, nullptr, out);
}